// round 12
// baseline (speedup 1.0000x reference)
#include <cuda_runtime.h>
#include <cuda_fp16.h>
#include <cstdint>
#include <math.h>
#include <float.h>

#define SEQ 4096
#define DMODEL 1280
#define NHEAD 20
#define HDIM 64
#define FFN 5120
#define NSEG 8
#define LN_EPS 1e-5f
#define D3 (3 * DMODEL)

typedef unsigned int u32;
typedef __half f16;

// ---------------------------------------------------------------------------
// Scratch (device globals; no runtime allocation allowed)
// ---------------------------------------------------------------------------
__device__ f16   g_qkv[SEQ * D3];
__device__ float g_h[SEQ * DMODEL];
__device__ f16   g_xln[SEQ * DMODEL];
__device__ f16   g_attn[SEQ * DMODEL];
__device__ f16   g_yln[SEQ * DMODEL];
__device__ f16   g_ffn[SEQ * FFN];
__device__ f16   g_wqkv[DMODEL * D3];
__device__ float g_bqkv[D3];
__device__ f16   g_wo[DMODEL * DMODEL];
__device__ f16   g_wf1[DMODEL * FFN];
__device__ f16   g_wf2[FFN * DMODEL];

// ---------------------------------------------------------------------------
// fp32 -> fp16 convert (float4 granularity)
// ---------------------------------------------------------------------------
__global__ __launch_bounds__(256) void cvt_kernel(const float* __restrict__ src,
                                                  f16* __restrict__ dst, int n4) {
    int i = blockIdx.x * 256 + threadIdx.x;
    if (i < n4) {
        float4 v = *(const float4*)(src + (size_t)i * 4);
        __half2* dp = (__half2*)(dst + (size_t)i * 4);
        dp[0] = __floats2half2_rn(v.x, v.y);
        dp[1] = __floats2half2_rn(v.z, v.w);
    }
}

// convert + pack a [R x C] fp32 weight into fp16 dst with row stride ldd at column off
__global__ __launch_bounds__(256) void cvt_pack_kernel(const float* __restrict__ src,
                                                       f16* __restrict__ dst,
                                                       int c4, int n4, int ldd, int off) {
    int i = blockIdx.x * 256 + threadIdx.x;
    if (i < n4) {
        float4 v = *(const float4*)(src + (size_t)i * 4);
        int row = i / c4;
        int col = (i - row * c4) * 4;
        __half2* dp = (__half2*)(dst + (size_t)row * ldd + off + col);
        dp[0] = __floats2half2_rn(v.x, v.y);
        dp[1] = __floats2half2_rn(v.z, v.w);
    }
}

// pack QKV bias: [bq | 0 | bv] (fp32)
__global__ __launch_bounds__(256) void pack_bias_kernel(const float* __restrict__ bq,
                                                        const float* __restrict__ bv,
                                                        float* __restrict__ dst) {
    int i = blockIdx.x * 256 + threadIdx.x;
    if (i < D3) {
        float v = 0.f;
        if (i < DMODEL) v = bq[i];
        else if (i >= 2 * DMODEL) v = bv[i - 2 * DMODEL];
        dst[i] = v;
    }
}

// ---------------------------------------------------------------------------
// LayerNorm -> fp16 output
// ---------------------------------------------------------------------------
__global__ __launch_bounds__(256) void ln_kernel(const float* __restrict__ x,
                                                 const float* __restrict__ gam,
                                                 const float* __restrict__ bet,
                                                 f16* __restrict__ outp) {
    int r = blockIdx.x;
    const float* xr = x + (size_t)r * DMODEL;
    f16* outr = outp + (size_t)r * DMODEL;
    int tid = threadIdx.x;

    float s = 0.f, s2 = 0.f;
    for (int i = tid; i < DMODEL; i += 256) {
        float v = xr[i];
        s += v;
        s2 += v * v;
    }
    for (int off = 16; off > 0; off >>= 1) {
        s  += __shfl_xor_sync(0xffffffff, s, off);
        s2 += __shfl_xor_sync(0xffffffff, s2, off);
    }
    __shared__ float ss[8];
    __shared__ float ss2[8];
    int wid = tid >> 5;
    int lane = tid & 31;
    if (lane == 0) { ss[wid] = s; ss2[wid] = s2; }
    __syncthreads();
    if (wid == 0) {
        s  = (lane < 8) ? ss[lane]  : 0.f;
        s2 = (lane < 8) ? ss2[lane] : 0.f;
        for (int off = 4; off > 0; off >>= 1) {
            s  += __shfl_xor_sync(0xffffffff, s, off);
            s2 += __shfl_xor_sync(0xffffffff, s2, off);
        }
        if (lane == 0) { ss[0] = s; ss2[0] = s2; }
    }
    __syncthreads();
    float mu = ss[0] * (1.0f / DMODEL);
    float var = ss2[0] * (1.0f / DMODEL) - mu * mu;
    float inv = rsqrtf(var + LN_EPS);
    for (int i = tid; i < DMODEL; i += 256) {
        float v = (xr[i] - mu) * inv * gam[i] + bet[i];
        outr[i] = __float2half_rn(v);
    }
}

// ---------------------------------------------------------------------------
// fp16 tensor-core GEMM: C[M,N] = A[M,K] @ B[K,N] (+bias)(+gelu|+res)
// BM=128 BN=128 BK=32, 8 warps (4x2), warp tile 32x64, m16n8k16 f16 mma.
// 3-stage cp.async pipeline, ONE __syncthreads per k-tile.
// OUTMODE: 0 = fp32, 2 = fp16
// ---------------------------------------------------------------------------
#define EPI_BIAS 0
#define EPI_GELU 1
#define EPI_RES  2

#define APITCH 40
#define BPITCH 136
#define A_STG_H (128 * APITCH)
#define B_STG_H (32 * BPITCH)
#define HG_SMEM ((3 * A_STG_H + 3 * B_STG_H) * 2)

__device__ __forceinline__ void ldsm_x4(u32& r0, u32& r1, u32& r2, u32& r3, u32 addr) {
    asm volatile("ldmatrix.sync.aligned.m8n8.x4.shared.b16 {%0,%1,%2,%3},[%4];\n"
                 : "=r"(r0), "=r"(r1), "=r"(r2), "=r"(r3) : "r"(addr));
}
__device__ __forceinline__ void ldsm_x4_t(u32& r0, u32& r1, u32& r2, u32& r3, u32 addr) {
    asm volatile("ldmatrix.sync.aligned.m8n8.x4.trans.shared.b16 {%0,%1,%2,%3},[%4];\n"
                 : "=r"(r0), "=r"(r1), "=r"(r2), "=r"(r3) : "r"(addr));
}
__device__ __forceinline__ void mma_f16(float* c, const u32* a, u32 b0, u32 b1) {
    asm volatile(
        "mma.sync.aligned.m16n8k16.row.col.f32.f16.f16.f32 "
        "{%0,%1,%2,%3},{%4,%5,%6,%7},{%8,%9},{%0,%1,%2,%3};\n"
        : "+f"(c[0]), "+f"(c[1]), "+f"(c[2]), "+f"(c[3])
        : "r"(a[0]), "r"(a[1]), "r"(a[2]), "r"(a[3]), "r"(b0), "r"(b1));
}
__device__ __forceinline__ void mma_f16_s(float* c, u32 a0, u32 a1, u32 a2, u32 a3,
                                          u32 b0, u32 b1) {
    asm volatile(
        "mma.sync.aligned.m16n8k16.row.col.f32.f16.f16.f32 "
        "{%0,%1,%2,%3},{%4,%5,%6,%7},{%8,%9},{%0,%1,%2,%3};\n"
        : "+f"(c[0]), "+f"(c[1]), "+f"(c[2]), "+f"(c[3])
        : "r"(a0), "r"(a1), "r"(a2), "r"(a3), "r"(b0), "r"(b1));
}
__device__ __forceinline__ void cp_async16(u32 dst, const void* src) {
    asm volatile("cp.async.cg.shared.global [%0],[%1],16;\n" :: "r"(dst), "l"(src));
}
__device__ __forceinline__ void cp_commit() {
    asm volatile("cp.async.commit_group;\n");
}
__device__ __forceinline__ void cp_wait1() {
    asm volatile("cp.async.wait_group 1;\n");
}
__device__ __forceinline__ void cp_wait0() {
    asm volatile("cp.async.wait_group 0;\n");
}

__device__ __forceinline__ void hg_load_tile(
    const f16* A, const f16* B, f16* As_s, f16* Bs_s,
    int k0, int bm, int bn, int K, int N,
    int a_ld_row, int a_ld_col, int b_ld_row, int b_ld_col) {
    u32 d0 = (u32)__cvta_generic_to_shared(As_s + a_ld_row * APITCH + a_ld_col);
    cp_async16(d0, A + (size_t)(bm * 128 + a_ld_row) * K + k0 + a_ld_col);
    u32 d1 = (u32)__cvta_generic_to_shared(As_s + (a_ld_row + 64) * APITCH + a_ld_col);
    cp_async16(d1, A + (size_t)(bm * 128 + a_ld_row + 64) * K + k0 + a_ld_col);
    u32 d2 = (u32)__cvta_generic_to_shared(Bs_s + b_ld_row * BPITCH + b_ld_col);
    cp_async16(d2, B + (size_t)(k0 + b_ld_row) * N + bn * 128 + b_ld_col);
    u32 d3 = (u32)__cvta_generic_to_shared(Bs_s + (b_ld_row + 16) * BPITCH + b_ld_col);
    cp_async16(d3, B + (size_t)(k0 + b_ld_row + 16) * N + bn * 128 + b_ld_col);
}

template <int EPI, int OUTMODE>
__global__ __launch_bounds__(256) void hgemm_kernel(
    const f16* __restrict__ A, const f16* __restrict__ B,
    const float* __restrict__ bias, const float* __restrict__ res,
    void* __restrict__ Cout, int M, int N, int K) {
    extern __shared__ f16 smh[];
    f16* As = smh;                     // 3 stages of 128 x APITCH
    f16* Bs = smh + 3 * A_STG_H;       // 3 stages of 32 x BPITCH

    int tid = threadIdx.x;
    int bm = blockIdx.y;
    int bn = blockIdx.x;
    int lane = tid & 31;
    int warp = tid >> 5;
    int wm = warp >> 1;
    int wn = warp & 1;

    int a_ld_row = tid >> 2;
    int a_ld_col = (tid & 3) * 8;
    int b_ld_row = tid >> 4;
    int b_ld_col = (tid & 15) * 8;

    float acc[2][8][4];
#pragma unroll
    for (int mi = 0; mi < 2; mi++) {
#pragma unroll
        for (int nj = 0; nj < 8; nj++) {
#pragma unroll
            for (int e = 0; e < 4; e++) acc[mi][nj][e] = 0.f;
        }
    }

    int KT = K / 32;

    // prologue: stages 0 and 1 in flight
    hg_load_tile(A, B, As, Bs, 0, bm, bn, K, N,
                 a_ld_row, a_ld_col, b_ld_row, b_ld_col);
    cp_commit();
    if (KT > 1) {
        hg_load_tile(A, B, As + A_STG_H, Bs + B_STG_H, 32, bm, bn, K, N,
                     a_ld_row, a_ld_col, b_ld_row, b_ld_col);
        cp_commit();
    }

    int a_row = wm * 32 + (lane & 15);
    int a_csel = (lane >> 4) * 8;
    int b_row = (lane & 15);
    int b_csel = wn * 64 + (lane >> 4) * 8;

    int s = 0;
    for (int kt = 0; kt < KT; kt++) {
        if (kt + 1 < KT) {
            cp_wait1();
        } else {
            cp_wait0();
        }
        __syncthreads();

        if (kt + 2 < KT) {
            int s2 = s + 2;
            if (s2 >= 3) s2 -= 3;
            hg_load_tile(A, B, As + s2 * A_STG_H, Bs + s2 * B_STG_H,
                         (kt + 2) * 32, bm, bn, K, N,
                         a_ld_row, a_ld_col, b_ld_row, b_ld_col);
            cp_commit();
        }

        f16* As_s = As + s * A_STG_H;
        f16* Bs_s = Bs + s * B_STG_H;

#pragma unroll
        for (int kk = 0; kk < 2; kk++) {
            u32 a_frag[2][4];
            u32 b_frag[4][4];
#pragma unroll
            for (int mi = 0; mi < 2; mi++) {
                u32 addr = (u32)__cvta_generic_to_shared(
                    As_s + (a_row + mi * 16) * APITCH + kk * 16 + a_csel);
                ldsm_x4(a_frag[mi][0], a_frag[mi][1], a_frag[mi][2], a_frag[mi][3], addr);
            }
#pragma unroll
            for (int nj = 0; nj < 4; nj++) {
                u32 addr = (u32)__cvta_generic_to_shared(
                    Bs_s + (kk * 16 + b_row) * BPITCH + nj * 16 + b_csel);
                ldsm_x4_t(b_frag[nj][0], b_frag[nj][1], b_frag[nj][2], b_frag[nj][3], addr);
            }
#pragma unroll
            for (int mi = 0; mi < 2; mi++) {
#pragma unroll
                for (int nj = 0; nj < 4; nj++) {
                    mma_f16(acc[mi][2 * nj],     a_frag[mi], b_frag[nj][0], b_frag[nj][1]);
                    mma_f16(acc[mi][2 * nj + 1], a_frag[mi], b_frag[nj][2], b_frag[nj][3]);
                }
            }
        }
        s = s + 1;
        if (s >= 3) s = 0;
    }

    // ---- epilogue ----
    int gID = lane >> 2;
    int tig = lane & 3;
#pragma unroll
    for (int mi = 0; mi < 2; mi++) {
        int row0 = bm * 128 + wm * 32 + mi * 16 + gID;
#pragma unroll
        for (int nj = 0; nj < 8; nj++) {
            int col = bn * 128 + wn * 64 + nj * 8 + tig * 2;
            float v0 = acc[mi][nj][0];
            float v1 = acc[mi][nj][1];
            float v2 = acc[mi][nj][2];
            float v3 = acc[mi][nj][3];
            if (bias != 0) {
                float b0 = bias[col];
                float b1 = bias[col + 1];
                v0 += b0; v1 += b1; v2 += b0; v3 += b1;
            }
            if (EPI == EPI_GELU) {
                v0 = 0.5f * v0 * (1.0f + erff(v0 * 0.70710678118654752f));
                v1 = 0.5f * v1 * (1.0f + erff(v1 * 0.70710678118654752f));
                v2 = 0.5f * v2 * (1.0f + erff(v2 * 0.70710678118654752f));
                v3 = 0.5f * v3 * (1.0f + erff(v3 * 0.70710678118654752f));
            }
            if (EPI == EPI_RES) {
                v0 += res[(size_t)row0 * N + col];
                v1 += res[(size_t)row0 * N + col + 1];
                v2 += res[(size_t)(row0 + 8) * N + col];
                v3 += res[(size_t)(row0 + 8) * N + col + 1];
            }
            if (OUTMODE == 2) {
                f16* C = (f16*)Cout;
                *(__half2*)(C + (size_t)row0 * N + col) = __floats2half2_rn(v0, v1);
                *(__half2*)(C + (size_t)(row0 + 8) * N + col) = __floats2half2_rn(v2, v3);
            } else {
                float* C = (float*)Cout;
                C[(size_t)row0 * N + col] = v0;
                C[(size_t)row0 * N + col + 1] = v1;
                C[(size_t)(row0 + 8) * N + col] = v2;
                C[(size_t)(row0 + 8) * N + col + 1] = v3;
            }
        }
    }
}

// ---------------------------------------------------------------------------
// Block-diagonal attention, fp16 tensor-core (verified round 10)
// ---------------------------------------------------------------------------
#define SPITCH 516
#define PPITCH 520
#define QKPITCH 72
#define ATT_SMEM_BYTES (64 * SPITCH * 4 + 64 * PPITCH * 2 + 2 * 64 * QKPITCH * 2)

__global__ __launch_bounds__(256) void attn_kernel(
    const f16* __restrict__ q, const f16* __restrict__ k,
    const f16* __restrict__ v, const int* __restrict__ cu,
    f16* __restrict__ outp, int ldqkv) {
    extern __shared__ char smraw[];
    float* sc = (float*)smraw;
    f16* Pb  = (f16*)(smraw + 64 * SPITCH * 4);
    f16* Qs  = Pb + 64 * PPITCH;
    f16* KVs = Qs + 64 * QKPITCH;

    int h = blockIdx.y;
    int q0 = blockIdx.x * 64;

    int g = 0;
    for (int i = 0; i < NSEG; i++) {
        if (cu[i] <= q0) g = i;
    }
    int s0 = cu[g];
    int s1 = cu[g + 1];
    int len = s1 - s0;
    if (len > 512) len = 512;
    int nchunks = (len + 63) >> 6;

    int tid = threadIdx.x;
    int lane = tid & 31;
    int warp = tid >> 5;
    int wm = warp >> 1;
    int wn = warp & 1;
    int gID = lane >> 2;
    int tig = lane & 3;
    const float scale = 0.125f;

#pragma unroll
    for (int t = 0; t < 2; t++) {
        int gi = tid + t * 256;
        int i = gi >> 3;
        int c8 = (gi & 7) * 8;
        uint4 qv = *(const uint4*)(q + (size_t)(q0 + i) * ldqkv + h * HDIM + c8);
        *(uint4*)(Qs + i * QKPITCH + c8) = qv;
    }
    __syncthreads();

    int m0 = wm * 16;
    u32 qa[4][4];
#pragma unroll
    for (int ks = 0; ks < 4; ks++) {
        u32 addr = (u32)__cvta_generic_to_shared(
            Qs + (m0 + (lane & 15)) * QKPITCH + ks * 16 + (lane >> 4) * 8);
        ldsm_x4(qa[ks][0], qa[ks][1], qa[ks][2], qa[ks][3], addr);
    }

    for (int c = 0; c < nchunks; c++) {
        __syncthreads();
#pragma unroll
        for (int t = 0; t < 2; t++) {
            int gi = tid + t * 256;
            int j = gi >> 3;
            int c8 = (gi & 7) * 8;
            int krow = s0 + c * 64 + j;
            uint4 kv = make_uint4(0u, 0u, 0u, 0u);
            if (krow < s1) {
                kv = *(const uint4*)(k + (size_t)krow * ldqkv + h * HDIM + c8);
            }
            *(uint4*)(KVs + j * QKPITCH + c8) = kv;
        }
        __syncthreads();

        float acc[4][4];
#pragma unroll
        for (int nt = 0; nt < 4; nt++) {
#pragma unroll
            for (int e = 0; e < 4; e++) acc[nt][e] = 0.f;
        }
#pragma unroll
        for (int ks = 0; ks < 4; ks++) {
#pragma unroll
            for (int nt16 = 0; nt16 < 2; nt16++) {
                int j0w = wn * 32 + nt16 * 16;
                u32 r0, r1, r2, r3;
                u32 addr = (u32)__cvta_generic_to_shared(
                    KVs + (j0w + (lane & 15)) * QKPITCH + ks * 16 + (lane >> 4) * 8);
                ldsm_x4(r0, r1, r2, r3, addr);
                mma_f16_s(acc[nt16 * 2],     qa[ks][0], qa[ks][1], qa[ks][2], qa[ks][3], r0, r2);
                mma_f16_s(acc[nt16 * 2 + 1], qa[ks][0], qa[ks][1], qa[ks][2], qa[ks][3], r1, r3);
            }
        }
        int row0 = m0 + gID;
#pragma unroll
        for (int nt = 0; nt < 4; nt++) {
            int col = c * 64 + wn * 32 + nt * 8 + tig * 2;
            sc[row0 * SPITCH + col]           = acc[nt][0] * scale;
            sc[row0 * SPITCH + col + 1]       = acc[nt][1] * scale;
            sc[(row0 + 8) * SPITCH + col]     = acc[nt][2] * scale;
            sc[(row0 + 8) * SPITCH + col + 1] = acc[nt][3] * scale;
        }
    }
    __syncthreads();

    int padlen = nchunks * 64;
    for (int r = warp; r < 64; r += 8) {
        float* row = sc + r * SPITCH;
        f16* prow = Pb + r * PPITCH;
        float m = -FLT_MAX;
        for (int j = lane; j < len; j += 32) m = fmaxf(m, row[j]);
        for (int off = 16; off > 0; off >>= 1) {
            m = fmaxf(m, __shfl_xor_sync(0xffffffff, m, off));
        }
        float s = 0.f;
        for (int j = lane; j < len; j += 32) {
            float e = __expf(row[j] - m);
            row[j] = e;
            s += e;
        }
        for (int off = 16; off > 0; off >>= 1) {
            s += __shfl_xor_sync(0xffffffff, s, off);
        }
        float inv = 1.0f / s;
        for (int j = lane; j < len; j += 32) prow[j] = __float2half_rn(row[j] * inv);
        for (int j = len + lane; j < padlen; j += 32) prow[j] = __float2half_rn(0.f);
    }
    __syncthreads();

    float acco[4][4];
#pragma unroll
    for (int nt = 0; nt < 4; nt++) {
#pragma unroll
        for (int e = 0; e < 4; e++) acco[nt][e] = 0.f;
    }

    for (int c = 0; c < nchunks; c++) {
        __syncthreads();
#pragma unroll
        for (int t = 0; t < 2; t++) {
            int gi = tid + t * 256;
            int j = gi >> 3;
            int c8 = (gi & 7) * 8;
            int vrow = s0 + c * 64 + j;
            uint4 vv = make_uint4(0u, 0u, 0u, 0u);
            if (vrow < s1) {
                vv = *(const uint4*)(v + (size_t)vrow * ldqkv + h * HDIM + c8);
            }
            *(uint4*)(KVs + j * QKPITCH + c8) = vv;
        }
        __syncthreads();

#pragma unroll
        for (int ks = 0; ks < 4; ks++) {
            int kg = c * 64 + ks * 16;
            int kl = ks * 16;
            u32 pa0, pa1, pa2, pa3;
            u32 paddr = (u32)__cvta_generic_to_shared(
                Pb + (m0 + (lane & 15)) * PPITCH + kg + (lane >> 4) * 8);
            ldsm_x4(pa0, pa1, pa2, pa3, paddr);
#pragma unroll
            for (int nt16 = 0; nt16 < 2; nt16++) {
                int n0 = wn * 32 + nt16 * 16;
                u32 b0, b1, b2, b3;
                u32 vaddr = (u32)__cvta_generic_to_shared(
                    KVs + (kl + (lane & 15)) * QKPITCH + n0 + (lane >> 4) * 8);
                ldsm_x4_t(b0, b1, b2, b3, vaddr);
                mma_f16_s(acco[nt16 * 2],     pa0, pa1, pa2, pa3, b0, b1);
                mma_f16_s(acco[nt16 * 2 + 1], pa0, pa1, pa2, pa3, b2, b3);
            }
        }
    }

    int orow0 = q0 + m0 + gID;
#pragma unroll
    for (int nt = 0; nt < 4; nt++) {
        int col = h * HDIM + wn * 32 + nt * 8 + tig * 2;
        *(__half2*)(outp + (size_t)orow0 * DMODEL + col) =
            __floats2half2_rn(acco[nt][0], acco[nt][1]);
        *(__half2*)(outp + (size_t)(orow0 + 8) * DMODEL + col) =
            __floats2half2_rn(acco[nt][2], acco[nt][3]);
    }
}

// ---------------------------------------------------------------------------
// launch
// ---------------------------------------------------------------------------
extern "C" void kernel_launch(void* const* d_in, const int* in_sizes, int n_in,
                              void* d_out, int out_size) {
    const float* hidden = (const float*)d_in[0];
    const int*   cu     = (const int*)d_in[1];
    const float* Wq = (const float*)d_in[2];
    const float* bq = (const float*)d_in[3];
    const float* Wk = (const float*)d_in[4];
    const float* Wv = (const float*)d_in[5];
    const float* bv = (const float*)d_in[6];
    const float* Wo = (const float*)d_in[7];
    const float* bo = (const float*)d_in[8];
    const float* ln1_g = (const float*)d_in[9];
    const float* ln1_b = (const float*)d_in[10];
    const float* Wf1 = (const float*)d_in[11];
    const float* bf1 = (const float*)d_in[12];
    const float* Wf2 = (const float*)d_in[13];
    const float* bf2 = (const float*)d_in[14];
    const float* ln2_g = (const float*)d_in[15];
    const float* ln2_b = (const float*)d_in[16];
    float* out = (float*)d_out;

    float *hp, *bqkvp;
    f16 *qkvp, *xlnp, *attnp, *ylnp, *ffnp, *wqkvp, *wop, *wf1p, *wf2p;
    cudaGetSymbolAddress((void**)&qkvp,  g_qkv);
    cudaGetSymbolAddress((void**)&hp,    g_h);
    cudaGetSymbolAddress((void**)&bqkvp, g_bqkv);
    cudaGetSymbolAddress((void**)&xlnp,  g_xln);
    cudaGetSymbolAddress((void**)&attnp, g_attn);
    cudaGetSymbolAddress((void**)&ylnp,  g_yln);
    cudaGetSymbolAddress((void**)&ffnp,  g_ffn);
    cudaGetSymbolAddress((void**)&wqkvp, g_wqkv);
    cudaGetSymbolAddress((void**)&wop,   g_wo);
    cudaGetSymbolAddress((void**)&wf1p,  g_wf1);
    cudaGetSymbolAddress((void**)&wf2p,  g_wf2);

    static bool attr_set = false;
    if (!attr_set) {
        cudaFuncSetAttribute(attn_kernel, cudaFuncAttributeMaxDynamicSharedMemorySize,
                             ATT_SMEM_BYTES);
        cudaFuncSetAttribute(hgemm_kernel<EPI_BIAS, 2>,
                             cudaFuncAttributeMaxDynamicSharedMemorySize, HG_SMEM);
        cudaFuncSetAttribute(hgemm_kernel<EPI_RES, 0>,
                             cudaFuncAttributeMaxDynamicSharedMemorySize, HG_SMEM);
        cudaFuncSetAttribute(hgemm_kernel<EPI_GELU, 2>,
                             cudaFuncAttributeMaxDynamicSharedMemorySize, HG_SMEM);
        attr_set = true;
    }

    dim3 blk(256);
    int nDD4 = DMODEL * DMODEL / 4;
    int nDF4 = DMODEL * FFN / 4;
    int c4 = DMODEL / 4;
    cvt_pack_kernel<<<(nDD4 + 255) / 256, blk>>>(Wq, wqkvp, c4, nDD4, D3, 0);
    cvt_pack_kernel<<<(nDD4 + 255) / 256, blk>>>(Wk, wqkvp, c4, nDD4, D3, DMODEL);
    cvt_pack_kernel<<<(nDD4 + 255) / 256, blk>>>(Wv, wqkvp, c4, nDD4, D3, 2 * DMODEL);
    pack_bias_kernel<<<(D3 + 255) / 256, blk>>>(bq, bv, bqkvp);
    cvt_kernel<<<(nDD4 + 255) / 256, blk>>>(Wo,  wop,  nDD4);
    cvt_kernel<<<(nDF4 + 255) / 256, blk>>>(Wf1, wf1p, nDF4);
    cvt_kernel<<<(nDF4 + 255) / 256, blk>>>(Wf2, wf2p, nDF4);

    dim3 gemmQKV(D3 / 128, SEQ / 128);
    dim3 gemmDD(DMODEL / 128, SEQ / 128);
    dim3 gemmDF(FFN / 128, SEQ / 128);

    ln_kernel<<<SEQ, blk>>>(hidden, ln1_g, ln1_b, xlnp);
    hgemm_kernel<EPI_BIAS, 2><<<gemmQKV, blk, HG_SMEM>>>(
        xlnp, wqkvp, bqkvp, 0, qkvp, SEQ, D3, DMODEL);
    attn_kernel<<<dim3(SEQ / 64, NHEAD), blk, ATT_SMEM_BYTES>>>(
        qkvp, qkvp + DMODEL, qkvp + 2 * DMODEL, cu, attnp, D3);
    hgemm_kernel<EPI_RES, 0><<<gemmDD, blk, HG_SMEM>>>(
        attnp, wop, bo, hidden, hp, SEQ, DMODEL, DMODEL);
    ln_kernel<<<SEQ, blk>>>(hp, ln2_g, ln2_b, ylnp);
    hgemm_kernel<EPI_GELU, 2><<<gemmDF, blk, HG_SMEM>>>(
        ylnp, wf1p, bf1, 0, ffnp, SEQ, FFN, DMODEL);
    hgemm_kernel<EPI_RES, 0><<<gemmDD, blk, HG_SMEM>>>(
        ffnp, wf2p, bf2, hp, out, SEQ, DMODEL, FFN);
}

// round 13
// speedup vs baseline: 1.0035x; 1.0035x over previous
#include <cuda_runtime.h>
#include <cuda_fp16.h>
#include <cstdint>
#include <math.h>
#include <float.h>

#define SEQ 4096
#define DMODEL 1280
#define NHEAD 20
#define HDIM 64
#define FFN 5120
#define NSEG 8
#define LN_EPS 1e-5f
#define D3 (3 * DMODEL)

typedef unsigned int u32;
typedef __half f16;

// ---------------------------------------------------------------------------
// Scratch (device globals; no runtime allocation allowed)
// ---------------------------------------------------------------------------
__device__ f16   g_qkv[SEQ * D3];
__device__ float g_h[SEQ * DMODEL];
__device__ f16   g_xln[SEQ * DMODEL];
__device__ f16   g_attn[SEQ * DMODEL];
__device__ f16   g_yln[SEQ * DMODEL];
__device__ f16   g_ffn[SEQ * FFN];
__device__ f16   g_wqkv[DMODEL * D3];
__device__ float g_bqkv[D3];
__device__ f16   g_wo[DMODEL * DMODEL];
__device__ f16   g_wf1[DMODEL * FFN];
__device__ f16   g_wf2[FFN * DMODEL];

// ---------------------------------------------------------------------------
// fp32 -> fp16 convert (float4 granularity)
// ---------------------------------------------------------------------------
__global__ __launch_bounds__(256) void cvt_kernel(const float* __restrict__ src,
                                                  f16* __restrict__ dst, int n4) {
    int i = blockIdx.x * 256 + threadIdx.x;
    if (i < n4) {
        float4 v = *(const float4*)(src + (size_t)i * 4);
        __half2* dp = (__half2*)(dst + (size_t)i * 4);
        dp[0] = __floats2half2_rn(v.x, v.y);
        dp[1] = __floats2half2_rn(v.z, v.w);
    }
}

// convert + pack a [R x C] fp32 weight into fp16 dst with row stride ldd at column off
__global__ __launch_bounds__(256) void cvt_pack_kernel(const float* __restrict__ src,
                                                       f16* __restrict__ dst,
                                                       int c4, int n4, int ldd, int off) {
    int i = blockIdx.x * 256 + threadIdx.x;
    if (i < n4) {
        float4 v = *(const float4*)(src + (size_t)i * 4);
        int row = i / c4;
        int col = (i - row * c4) * 4;
        __half2* dp = (__half2*)(dst + (size_t)row * ldd + off + col);
        dp[0] = __floats2half2_rn(v.x, v.y);
        dp[1] = __floats2half2_rn(v.z, v.w);
    }
}

// pack QKV bias: [bq | 0 | bv] (fp32)
__global__ __launch_bounds__(256) void pack_bias_kernel(const float* __restrict__ bq,
                                                        const float* __restrict__ bv,
                                                        float* __restrict__ dst) {
    int i = blockIdx.x * 256 + threadIdx.x;
    if (i < D3) {
        float v = 0.f;
        if (i < DMODEL) v = bq[i];
        else if (i >= 2 * DMODEL) v = bv[i - 2 * DMODEL];
        dst[i] = v;
    }
}

// ---------------------------------------------------------------------------
// LayerNorm -> fp16 output
// ---------------------------------------------------------------------------
__global__ __launch_bounds__(256) void ln_kernel(const float* __restrict__ x,
                                                 const float* __restrict__ gam,
                                                 const float* __restrict__ bet,
                                                 f16* __restrict__ outp) {
    int r = blockIdx.x;
    const float* xr = x + (size_t)r * DMODEL;
    f16* outr = outp + (size_t)r * DMODEL;
    int tid = threadIdx.x;

    float s = 0.f, s2 = 0.f;
    for (int i = tid; i < DMODEL; i += 256) {
        float v = xr[i];
        s += v;
        s2 += v * v;
    }
    for (int off = 16; off > 0; off >>= 1) {
        s  += __shfl_xor_sync(0xffffffff, s, off);
        s2 += __shfl_xor_sync(0xffffffff, s2, off);
    }
    __shared__ float ss[8];
    __shared__ float ss2[8];
    int wid = tid >> 5;
    int lane = tid & 31;
    if (lane == 0) { ss[wid] = s; ss2[wid] = s2; }
    __syncthreads();
    if (wid == 0) {
        s  = (lane < 8) ? ss[lane]  : 0.f;
        s2 = (lane < 8) ? ss2[lane] : 0.f;
        for (int off = 4; off > 0; off >>= 1) {
            s  += __shfl_xor_sync(0xffffffff, s, off);
            s2 += __shfl_xor_sync(0xffffffff, s2, off);
        }
        if (lane == 0) { ss[0] = s; ss2[0] = s2; }
    }
    __syncthreads();
    float mu = ss[0] * (1.0f / DMODEL);
    float var = ss2[0] * (1.0f / DMODEL) - mu * mu;
    float inv = rsqrtf(var + LN_EPS);
    for (int i = tid; i < DMODEL; i += 256) {
        float v = (xr[i] - mu) * inv * gam[i] + bet[i];
        outr[i] = __float2half_rn(v);
    }
}

// ---------------------------------------------------------------------------
// fp16 tensor-core GEMM: C[M,N] = A[M,K] @ B[K,N] (+bias)(+gelu|+res)
// BM=128 BN=128 BK=32, 8 warps (4x2), warp tile 32x64, m16n8k16 f16 mma.
// 2-stage cp.async pipeline (verified round 10 config).
// OUTMODE: 0 = fp32, 2 = fp16
// ---------------------------------------------------------------------------
#define EPI_BIAS 0
#define EPI_GELU 1
#define EPI_RES  2

#define APITCH 40
#define BPITCH 136

__device__ __forceinline__ void ldsm_x4(u32& r0, u32& r1, u32& r2, u32& r3, u32 addr) {
    asm volatile("ldmatrix.sync.aligned.m8n8.x4.shared.b16 {%0,%1,%2,%3},[%4];\n"
                 : "=r"(r0), "=r"(r1), "=r"(r2), "=r"(r3) : "r"(addr));
}
__device__ __forceinline__ void ldsm_x4_t(u32& r0, u32& r1, u32& r2, u32& r3, u32 addr) {
    asm volatile("ldmatrix.sync.aligned.m8n8.x4.trans.shared.b16 {%0,%1,%2,%3},[%4];\n"
                 : "=r"(r0), "=r"(r1), "=r"(r2), "=r"(r3) : "r"(addr));
}
__device__ __forceinline__ void mma_f16(float* c, const u32* a, u32 b0, u32 b1) {
    asm volatile(
        "mma.sync.aligned.m16n8k16.row.col.f32.f16.f16.f32 "
        "{%0,%1,%2,%3},{%4,%5,%6,%7},{%8,%9},{%0,%1,%2,%3};\n"
        : "+f"(c[0]), "+f"(c[1]), "+f"(c[2]), "+f"(c[3])
        : "r"(a[0]), "r"(a[1]), "r"(a[2]), "r"(a[3]), "r"(b0), "r"(b1));
}
__device__ __forceinline__ void mma_f16_s(float* c, u32 a0, u32 a1, u32 a2, u32 a3,
                                          u32 b0, u32 b1) {
    asm volatile(
        "mma.sync.aligned.m16n8k16.row.col.f32.f16.f16.f32 "
        "{%0,%1,%2,%3},{%4,%5,%6,%7},{%8,%9},{%0,%1,%2,%3};\n"
        : "+f"(c[0]), "+f"(c[1]), "+f"(c[2]), "+f"(c[3])
        : "r"(a0), "r"(a1), "r"(a2), "r"(a3), "r"(b0), "r"(b1));
}
__device__ __forceinline__ void cp_async16(u32 dst, const void* src) {
    asm volatile("cp.async.cg.shared.global [%0],[%1],16;\n" :: "r"(dst), "l"(src));
}
__device__ __forceinline__ void cp_commit() {
    asm volatile("cp.async.commit_group;\n");
}
__device__ __forceinline__ void cp_wait1() {
    asm volatile("cp.async.wait_group 1;\n");
}
__device__ __forceinline__ void cp_wait0() {
    asm volatile("cp.async.wait_group 0;\n");
}

__device__ __forceinline__ void hg_load_tile(
    const f16* A, const f16* B, f16* As_s, f16* Bs_s,
    int k0, int bm, int bn, int K, int N,
    int a_ld_row, int a_ld_col, int b_ld_row, int b_ld_col) {
    u32 d0 = (u32)__cvta_generic_to_shared(As_s + a_ld_row * APITCH + a_ld_col);
    cp_async16(d0, A + (size_t)(bm * 128 + a_ld_row) * K + k0 + a_ld_col);
    u32 d1 = (u32)__cvta_generic_to_shared(As_s + (a_ld_row + 64) * APITCH + a_ld_col);
    cp_async16(d1, A + (size_t)(bm * 128 + a_ld_row + 64) * K + k0 + a_ld_col);
    u32 d2 = (u32)__cvta_generic_to_shared(Bs_s + b_ld_row * BPITCH + b_ld_col);
    cp_async16(d2, B + (size_t)(k0 + b_ld_row) * N + bn * 128 + b_ld_col);
    u32 d3 = (u32)__cvta_generic_to_shared(Bs_s + (b_ld_row + 16) * BPITCH + b_ld_col);
    cp_async16(d3, B + (size_t)(k0 + b_ld_row + 16) * N + bn * 128 + b_ld_col);
}

template <int EPI, int OUTMODE>
__global__ __launch_bounds__(256) void hgemm_kernel(
    const f16* __restrict__ A, const f16* __restrict__ B,
    const float* __restrict__ bias, const float* __restrict__ res,
    void* __restrict__ Cout, int M, int N, int K) {
    __shared__ f16 As[2 * 128 * APITCH];
    __shared__ f16 Bs[2 * 32 * BPITCH];

    int tid = threadIdx.x;
    int bm = blockIdx.y;
    int bn = blockIdx.x;
    int lane = tid & 31;
    int warp = tid >> 5;
    int wm = warp >> 1;
    int wn = warp & 1;

    int a_ld_row = tid >> 2;
    int a_ld_col = (tid & 3) * 8;
    int b_ld_row = tid >> 4;
    int b_ld_col = (tid & 15) * 8;

    float acc[2][8][4];
#pragma unroll
    for (int mi = 0; mi < 2; mi++) {
#pragma unroll
        for (int nj = 0; nj < 8; nj++) {
#pragma unroll
            for (int e = 0; e < 4; e++) acc[mi][nj][e] = 0.f;
        }
    }

    int KT = K / 32;

    hg_load_tile(A, B, As, Bs, 0, bm, bn, K, N,
                 a_ld_row, a_ld_col, b_ld_row, b_ld_col);
    cp_commit();

    int a_row = wm * 32 + (lane & 15);
    int a_csel = (lane >> 4) * 8;
    int b_row = (lane & 15);
    int b_csel = wn * 64 + (lane >> 4) * 8;

    for (int kt = 0; kt < KT; kt++) {
        int s = kt & 1;
        if (kt + 1 < KT) {
            int s2 = s ^ 1;
            hg_load_tile(A, B, As + s2 * 128 * APITCH, Bs + s2 * 32 * BPITCH,
                         (kt + 1) * 32, bm, bn, K, N,
                         a_ld_row, a_ld_col, b_ld_row, b_ld_col);
            cp_commit();
            cp_wait1();
        } else {
            cp_wait0();
        }
        __syncthreads();

        f16* As_s = As + s * 128 * APITCH;
        f16* Bs_s = Bs + s * 32 * BPITCH;

#pragma unroll
        for (int kk = 0; kk < 2; kk++) {
            u32 a_frag[2][4];
            u32 b_frag[4][4];
#pragma unroll
            for (int mi = 0; mi < 2; mi++) {
                u32 addr = (u32)__cvta_generic_to_shared(
                    As_s + (a_row + mi * 16) * APITCH + kk * 16 + a_csel);
                ldsm_x4(a_frag[mi][0], a_frag[mi][1], a_frag[mi][2], a_frag[mi][3], addr);
            }
#pragma unroll
            for (int nj = 0; nj < 4; nj++) {
                u32 addr = (u32)__cvta_generic_to_shared(
                    Bs_s + (kk * 16 + b_row) * BPITCH + nj * 16 + b_csel);
                ldsm_x4_t(b_frag[nj][0], b_frag[nj][1], b_frag[nj][2], b_frag[nj][3], addr);
            }
#pragma unroll
            for (int mi = 0; mi < 2; mi++) {
#pragma unroll
                for (int nj = 0; nj < 4; nj++) {
                    mma_f16(acc[mi][2 * nj],     a_frag[mi], b_frag[nj][0], b_frag[nj][1]);
                    mma_f16(acc[mi][2 * nj + 1], a_frag[mi], b_frag[nj][2], b_frag[nj][3]);
                }
            }
        }
        __syncthreads();
    }

    // ---- epilogue ----
    int gID = lane >> 2;
    int tig = lane & 3;
#pragma unroll
    for (int mi = 0; mi < 2; mi++) {
        int row0 = bm * 128 + wm * 32 + mi * 16 + gID;
#pragma unroll
        for (int nj = 0; nj < 8; nj++) {
            int col = bn * 128 + wn * 64 + nj * 8 + tig * 2;
            float v0 = acc[mi][nj][0];
            float v1 = acc[mi][nj][1];
            float v2 = acc[mi][nj][2];
            float v3 = acc[mi][nj][3];
            if (bias != 0) {
                float b0 = bias[col];
                float b1 = bias[col + 1];
                v0 += b0; v1 += b1; v2 += b0; v3 += b1;
            }
            if (EPI == EPI_GELU) {
                v0 = 0.5f * v0 * (1.0f + erff(v0 * 0.70710678118654752f));
                v1 = 0.5f * v1 * (1.0f + erff(v1 * 0.70710678118654752f));
                v2 = 0.5f * v2 * (1.0f + erff(v2 * 0.70710678118654752f));
                v3 = 0.5f * v3 * (1.0f + erff(v3 * 0.70710678118654752f));
            }
            if (EPI == EPI_RES) {
                v0 += res[(size_t)row0 * N + col];
                v1 += res[(size_t)row0 * N + col + 1];
                v2 += res[(size_t)(row0 + 8) * N + col];
                v3 += res[(size_t)(row0 + 8) * N + col + 1];
            }
            if (OUTMODE == 2) {
                f16* C = (f16*)Cout;
                *(__half2*)(C + (size_t)row0 * N + col) = __floats2half2_rn(v0, v1);
                *(__half2*)(C + (size_t)(row0 + 8) * N + col) = __floats2half2_rn(v2, v3);
            } else {
                float* C = (float*)Cout;
                C[(size_t)row0 * N + col] = v0;
                C[(size_t)row0 * N + col + 1] = v1;
                C[(size_t)(row0 + 8) * N + col] = v2;
                C[(size_t)(row0 + 8) * N + col + 1] = v3;
            }
        }
    }
}

// ---------------------------------------------------------------------------
// Block-diagonal attention, fp16 tensor-core (verified round 10)
// ---------------------------------------------------------------------------
#define SPITCH 516
#define PPITCH 520
#define QKPITCH 72
#define ATT_SMEM_BYTES (64 * SPITCH * 4 + 64 * PPITCH * 2 + 2 * 64 * QKPITCH * 2)

__global__ __launch_bounds__(256) void attn_kernel(
    const f16* __restrict__ q, const f16* __restrict__ k,
    const f16* __restrict__ v, const int* __restrict__ cu,
    f16* __restrict__ outp, int ldqkv) {
    extern __shared__ char smraw[];
    float* sc = (float*)smraw;
    f16* Pb  = (f16*)(smraw + 64 * SPITCH * 4);
    f16* Qs  = Pb + 64 * PPITCH;
    f16* KVs = Qs + 64 * QKPITCH;

    int h = blockIdx.y;
    int q0 = blockIdx.x * 64;

    int g = 0;
    for (int i = 0; i < NSEG; i++) {
        if (cu[i] <= q0) g = i;
    }
    int s0 = cu[g];
    int s1 = cu[g + 1];
    int len = s1 - s0;
    if (len > 512) len = 512;
    int nchunks = (len + 63) >> 6;

    int tid = threadIdx.x;
    int lane = tid & 31;
    int warp = tid >> 5;
    int wm = warp >> 1;
    int wn = warp & 1;
    int gID = lane >> 2;
    int tig = lane & 3;
    const float scale = 0.125f;

#pragma unroll
    for (int t = 0; t < 2; t++) {
        int gi = tid + t * 256;
        int i = gi >> 3;
        int c8 = (gi & 7) * 8;
        uint4 qv = *(const uint4*)(q + (size_t)(q0 + i) * ldqkv + h * HDIM + c8);
        *(uint4*)(Qs + i * QKPITCH + c8) = qv;
    }
    __syncthreads();

    int m0 = wm * 16;
    u32 qa[4][4];
#pragma unroll
    for (int ks = 0; ks < 4; ks++) {
        u32 addr = (u32)__cvta_generic_to_shared(
            Qs + (m0 + (lane & 15)) * QKPITCH + ks * 16 + (lane >> 4) * 8);
        ldsm_x4(qa[ks][0], qa[ks][1], qa[ks][2], qa[ks][3], addr);
    }

    for (int c = 0; c < nchunks; c++) {
        __syncthreads();
#pragma unroll
        for (int t = 0; t < 2; t++) {
            int gi = tid + t * 256;
            int j = gi >> 3;
            int c8 = (gi & 7) * 8;
            int krow = s0 + c * 64 + j;
            uint4 kv = make_uint4(0u, 0u, 0u, 0u);
            if (krow < s1) {
                kv = *(const uint4*)(k + (size_t)krow * ldqkv + h * HDIM + c8);
            }
            *(uint4*)(KVs + j * QKPITCH + c8) = kv;
        }
        __syncthreads();

        float acc[4][4];
#pragma unroll
        for (int nt = 0; nt < 4; nt++) {
#pragma unroll
            for (int e = 0; e < 4; e++) acc[nt][e] = 0.f;
        }
#pragma unroll
        for (int ks = 0; ks < 4; ks++) {
#pragma unroll
            for (int nt16 = 0; nt16 < 2; nt16++) {
                int j0w = wn * 32 + nt16 * 16;
                u32 r0, r1, r2, r3;
                u32 addr = (u32)__cvta_generic_to_shared(
                    KVs + (j0w + (lane & 15)) * QKPITCH + ks * 16 + (lane >> 4) * 8);
                ldsm_x4(r0, r1, r2, r3, addr);
                mma_f16_s(acc[nt16 * 2],     qa[ks][0], qa[ks][1], qa[ks][2], qa[ks][3], r0, r2);
                mma_f16_s(acc[nt16 * 2 + 1], qa[ks][0], qa[ks][1], qa[ks][2], qa[ks][3], r1, r3);
            }
        }
        int row0 = m0 + gID;
#pragma unroll
        for (int nt = 0; nt < 4; nt++) {
            int col = c * 64 + wn * 32 + nt * 8 + tig * 2;
            sc[row0 * SPITCH + col]           = acc[nt][0] * scale;
            sc[row0 * SPITCH + col + 1]       = acc[nt][1] * scale;
            sc[(row0 + 8) * SPITCH + col]     = acc[nt][2] * scale;
            sc[(row0 + 8) * SPITCH + col + 1] = acc[nt][3] * scale;
        }
    }
    __syncthreads();

    int padlen = nchunks * 64;
    for (int r = warp; r < 64; r += 8) {
        float* row = sc + r * SPITCH;
        f16* prow = Pb + r * PPITCH;
        float m = -FLT_MAX;
        for (int j = lane; j < len; j += 32) m = fmaxf(m, row[j]);
        for (int off = 16; off > 0; off >>= 1) {
            m = fmaxf(m, __shfl_xor_sync(0xffffffff, m, off));
        }
        float s = 0.f;
        for (int j = lane; j < len; j += 32) {
            float e = __expf(row[j] - m);
            row[j] = e;
            s += e;
        }
        for (int off = 16; off > 0; off >>= 1) {
            s += __shfl_xor_sync(0xffffffff, s, off);
        }
        float inv = 1.0f / s;
        for (int j = lane; j < len; j += 32) prow[j] = __float2half_rn(row[j] * inv);
        for (int j = len + lane; j < padlen; j += 32) prow[j] = __float2half_rn(0.f);
    }
    __syncthreads();

    float acco[4][4];
#pragma unroll
    for (int nt = 0; nt < 4; nt++) {
#pragma unroll
        for (int e = 0; e < 4; e++) acco[nt][e] = 0.f;
    }

    for (int c = 0; c < nchunks; c++) {
        __syncthreads();
#pragma unroll
        for (int t = 0; t < 2; t++) {
            int gi = tid + t * 256;
            int j = gi >> 3;
            int c8 = (gi & 7) * 8;
            int vrow = s0 + c * 64 + j;
            uint4 vv = make_uint4(0u, 0u, 0u, 0u);
            if (vrow < s1) {
                vv = *(const uint4*)(v + (size_t)vrow * ldqkv + h * HDIM + c8);
            }
            *(uint4*)(KVs + j * QKPITCH + c8) = vv;
        }
        __syncthreads();

#pragma unroll
        for (int ks = 0; ks < 4; ks++) {
            int kg = c * 64 + ks * 16;
            int kl = ks * 16;
            u32 pa0, pa1, pa2, pa3;
            u32 paddr = (u32)__cvta_generic_to_shared(
                Pb + (m0 + (lane & 15)) * PPITCH + kg + (lane >> 4) * 8);
            ldsm_x4(pa0, pa1, pa2, pa3, paddr);
#pragma unroll
            for (int nt16 = 0; nt16 < 2; nt16++) {
                int n0 = wn * 32 + nt16 * 16;
                u32 b0, b1, b2, b3;
                u32 vaddr = (u32)__cvta_generic_to_shared(
                    KVs + (kl + (lane & 15)) * QKPITCH + n0 + (lane >> 4) * 8);
                ldsm_x4_t(b0, b1, b2, b3, vaddr);
                mma_f16_s(acco[nt16 * 2],     pa0, pa1, pa2, pa3, b0, b1);
                mma_f16_s(acco[nt16 * 2 + 1], pa0, pa1, pa2, pa3, b2, b3);
            }
        }
    }

    int orow0 = q0 + m0 + gID;
#pragma unroll
    for (int nt = 0; nt < 4; nt++) {
        int col = h * HDIM + wn * 32 + nt * 8 + tig * 2;
        *(__half2*)(outp + (size_t)orow0 * DMODEL + col) =
            __floats2half2_rn(acco[nt][0], acco[nt][1]);
        *(__half2*)(outp + (size_t)(orow0 + 8) * DMODEL + col) =
            __floats2half2_rn(acco[nt][2], acco[nt][3]);
    }
}

// ---------------------------------------------------------------------------
// launch — weight converts forked onto a side stream (graph-capturable
// fork/join with events; streams/events created once on first call)
// ---------------------------------------------------------------------------
extern "C" void kernel_launch(void* const* d_in, const int* in_sizes, int n_in,
                              void* d_out, int out_size) {
    const float* hidden = (const float*)d_in[0];
    const int*   cu     = (const int*)d_in[1];
    const float* Wq = (const float*)d_in[2];
    const float* bq = (const float*)d_in[3];
    const float* Wk = (const float*)d_in[4];
    const float* Wv = (const float*)d_in[5];
    const float* bv = (const float*)d_in[6];
    const float* Wo = (const float*)d_in[7];
    const float* bo = (const float*)d_in[8];
    const float* ln1_g = (const float*)d_in[9];
    const float* ln1_b = (const float*)d_in[10];
    const float* Wf1 = (const float*)d_in[11];
    const float* bf1 = (const float*)d_in[12];
    const float* Wf2 = (const float*)d_in[13];
    const float* bf2 = (const float*)d_in[14];
    const float* ln2_g = (const float*)d_in[15];
    const float* ln2_b = (const float*)d_in[16];
    float* out = (float*)d_out;

    float *hp, *bqkvp;
    f16 *qkvp, *xlnp, *attnp, *ylnp, *ffnp, *wqkvp, *wop, *wf1p, *wf2p;
    cudaGetSymbolAddress((void**)&qkvp,  g_qkv);
    cudaGetSymbolAddress((void**)&hp,    g_h);
    cudaGetSymbolAddress((void**)&bqkvp, g_bqkv);
    cudaGetSymbolAddress((void**)&xlnp,  g_xln);
    cudaGetSymbolAddress((void**)&attnp, g_attn);
    cudaGetSymbolAddress((void**)&ylnp,  g_yln);
    cudaGetSymbolAddress((void**)&ffnp,  g_ffn);
    cudaGetSymbolAddress((void**)&wqkvp, g_wqkv);
    cudaGetSymbolAddress((void**)&wop,   g_wo);
    cudaGetSymbolAddress((void**)&wf1p,  g_wf1);
    cudaGetSymbolAddress((void**)&wf2p,  g_wf2);

    static bool init_done = false;
    static cudaStream_t s_side;
    static cudaEvent_t ev_fork, ev_qkvw, ev_restw;
    if (!init_done) {
        cudaFuncSetAttribute(attn_kernel, cudaFuncAttributeMaxDynamicSharedMemorySize,
                             ATT_SMEM_BYTES);
        cudaStreamCreateWithFlags(&s_side, cudaStreamNonBlocking);
        cudaEventCreateWithFlags(&ev_fork,  cudaEventDisableTiming);
        cudaEventCreateWithFlags(&ev_qkvw,  cudaEventDisableTiming);
        cudaEventCreateWithFlags(&ev_restw, cudaEventDisableTiming);
        init_done = true;
    }

    dim3 blk(256);
    int nDD4 = DMODEL * DMODEL / 4;
    int nDF4 = DMODEL * FFN / 4;
    int c4 = DMODEL / 4;

    // fork: side stream does all weight conversions
    cudaEventRecord(ev_fork, 0);
    cudaStreamWaitEvent(s_side, ev_fork, 0);
    cvt_pack_kernel<<<(nDD4 + 255) / 256, blk, 0, s_side>>>(Wq, wqkvp, c4, nDD4, D3, 0);
    cvt_pack_kernel<<<(nDD4 + 255) / 256, blk, 0, s_side>>>(Wk, wqkvp, c4, nDD4, D3, DMODEL);
    cvt_pack_kernel<<<(nDD4 + 255) / 256, blk, 0, s_side>>>(Wv, wqkvp, c4, nDD4, D3, 2 * DMODEL);
    pack_bias_kernel<<<(D3 + 255) / 256, blk, 0, s_side>>>(bq, bv, bqkvp);
    cudaEventRecord(ev_qkvw, s_side);
    cvt_kernel<<<(nDD4 + 255) / 256, blk, 0, s_side>>>(Wo,  wop,  nDD4);
    cvt_kernel<<<(nDF4 + 255) / 256, blk, 0, s_side>>>(Wf1, wf1p, nDF4);
    cvt_kernel<<<(nDF4 + 255) / 256, blk, 0, s_side>>>(Wf2, wf2p, nDF4);
    cudaEventRecord(ev_restw, s_side);

    // main stream: LN1 runs concurrently with weight converts
    ln_kernel<<<SEQ, blk>>>(hidden, ln1_g, ln1_b, xlnp);

    dim3 gemmQKV(D3 / 128, SEQ / 128);
    dim3 gemmDD(DMODEL / 128, SEQ / 128);
    dim3 gemmDF(FFN / 128, SEQ / 128);

    // join QKV weights before the fused QKV GEMM
    cudaStreamWaitEvent(0, ev_qkvw, 0);
    hgemm_kernel<EPI_BIAS, 2><<<gemmQKV, blk>>>(
        xlnp, wqkvp, bqkvp, 0, qkvp, SEQ, D3, DMODEL);
    attn_kernel<<<dim3(SEQ / 64, NHEAD), blk, ATT_SMEM_BYTES>>>(
        qkvp, qkvp + DMODEL, qkvp + 2 * DMODEL, cu, attnp, D3);
    // join remaining weights before the O-projection
    cudaStreamWaitEvent(0, ev_restw, 0);
    hgemm_kernel<EPI_RES, 0><<<gemmDD, blk>>>(
        attnp, wop, bo, hidden, hp, SEQ, DMODEL, DMODEL);
    ln_kernel<<<SEQ, blk>>>(hp, ln2_g, ln2_b, ylnp);
    hgemm_kernel<EPI_GELU, 2><<<gemmDF, blk>>>(
        ylnp, wf1p, bf1, 0, ffnp, SEQ, FFN, DMODEL);
    hgemm_kernel<EPI_RES, 0><<<gemmDD, blk>>>(
        ffnp, wf2p, bf2, hp, out, SEQ, DMODEL, FFN);
}

// round 14
// speedup vs baseline: 1.2150x; 1.2107x over previous
#include <cuda_runtime.h>
#include <cuda_fp16.h>
#include <cstdint>
#include <math.h>
#include <float.h>

#define SEQ 4096
#define DMODEL 1280
#define NHEAD 20
#define HDIM 64
#define FFN 5120
#define NSEG 8
#define LN_EPS 1e-5f
#define D3 (3 * DMODEL)

typedef unsigned int u32;
typedef __half f16;

// ---------------------------------------------------------------------------
// Scratch (device globals; no runtime allocation allowed)
// ---------------------------------------------------------------------------
__device__ f16   g_qkv[SEQ * D3];
__device__ float g_h[SEQ * DMODEL];
__device__ f16   g_xln[SEQ * DMODEL];
__device__ f16   g_attn[SEQ * DMODEL];
__device__ f16   g_yln[SEQ * DMODEL];
__device__ f16   g_ffn[SEQ * FFN];
__device__ f16   g_wqkv[DMODEL * D3];
__device__ float g_bqkv[D3];
__device__ f16   g_wo[DMODEL * DMODEL];
__device__ f16   g_wf1[DMODEL * FFN];
__device__ f16   g_wf2[FFN * DMODEL];

// ---------------------------------------------------------------------------
// fp32 -> fp16 convert (float4 granularity)
// ---------------------------------------------------------------------------
__global__ __launch_bounds__(256) void cvt_kernel(const float* __restrict__ src,
                                                  f16* __restrict__ dst, int n4) {
    int i = blockIdx.x * 256 + threadIdx.x;
    if (i < n4) {
        float4 v = *(const float4*)(src + (size_t)i * 4);
        __half2* dp = (__half2*)(dst + (size_t)i * 4);
        dp[0] = __floats2half2_rn(v.x, v.y);
        dp[1] = __floats2half2_rn(v.z, v.w);
    }
}

// convert + pack a [R x C] fp32 weight into fp16 dst with row stride ldd at column off
__global__ __launch_bounds__(256) void cvt_pack_kernel(const float* __restrict__ src,
                                                       f16* __restrict__ dst,
                                                       int c4, int n4, int ldd, int off) {
    int i = blockIdx.x * 256 + threadIdx.x;
    if (i < n4) {
        float4 v = *(const float4*)(src + (size_t)i * 4);
        int row = i / c4;
        int col = (i - row * c4) * 4;
        __half2* dp = (__half2*)(dst + (size_t)row * ldd + off + col);
        dp[0] = __floats2half2_rn(v.x, v.y);
        dp[1] = __floats2half2_rn(v.z, v.w);
    }
}

// pack QKV bias: [bq | 0 | bv] (fp32)
__global__ __launch_bounds__(256) void pack_bias_kernel(const float* __restrict__ bq,
                                                        const float* __restrict__ bv,
                                                        float* __restrict__ dst) {
    int i = blockIdx.x * 256 + threadIdx.x;
    if (i < D3) {
        float v = 0.f;
        if (i < DMODEL) v = bq[i];
        else if (i >= 2 * DMODEL) v = bv[i - 2 * DMODEL];
        dst[i] = v;
    }
}

// ---------------------------------------------------------------------------
// LayerNorm -> fp16 output
// ---------------------------------------------------------------------------
__global__ __launch_bounds__(256) void ln_kernel(const float* __restrict__ x,
                                                 const float* __restrict__ gam,
                                                 const float* __restrict__ bet,
                                                 f16* __restrict__ outp) {
    int r = blockIdx.x;
    const float* xr = x + (size_t)r * DMODEL;
    f16* outr = outp + (size_t)r * DMODEL;
    int tid = threadIdx.x;

    float s = 0.f, s2 = 0.f;
    for (int i = tid; i < DMODEL; i += 256) {
        float v = xr[i];
        s += v;
        s2 += v * v;
    }
    for (int off = 16; off > 0; off >>= 1) {
        s  += __shfl_xor_sync(0xffffffff, s, off);
        s2 += __shfl_xor_sync(0xffffffff, s2, off);
    }
    __shared__ float ss[8];
    __shared__ float ss2[8];
    int wid = tid >> 5;
    int lane = tid & 31;
    if (lane == 0) { ss[wid] = s; ss2[wid] = s2; }
    __syncthreads();
    if (wid == 0) {
        s  = (lane < 8) ? ss[lane]  : 0.f;
        s2 = (lane < 8) ? ss2[lane] : 0.f;
        for (int off = 4; off > 0; off >>= 1) {
            s  += __shfl_xor_sync(0xffffffff, s, off);
            s2 += __shfl_xor_sync(0xffffffff, s2, off);
        }
        if (lane == 0) { ss[0] = s; ss2[0] = s2; }
    }
    __syncthreads();
    float mu = ss[0] * (1.0f / DMODEL);
    float var = ss2[0] * (1.0f / DMODEL) - mu * mu;
    float inv = rsqrtf(var + LN_EPS);
    for (int i = tid; i < DMODEL; i += 256) {
        float v = (xr[i] - mu) * inv * gam[i] + bet[i];
        outr[i] = __float2half_rn(v);
    }
}

// ---------------------------------------------------------------------------
// fp16 tensor-core GEMM (verified round 10): BM=128 BN=128 BK=32, 8 warps,
// warp tile 32x64, m16n8k16, 2-stage cp.async. OUTMODE: 0 = fp32, 2 = fp16
// ---------------------------------------------------------------------------
#define EPI_BIAS 0
#define EPI_GELU 1
#define EPI_RES  2

#define APITCH 40
#define BPITCH 136

__device__ __forceinline__ void ldsm_x4(u32& r0, u32& r1, u32& r2, u32& r3, u32 addr) {
    asm volatile("ldmatrix.sync.aligned.m8n8.x4.shared.b16 {%0,%1,%2,%3},[%4];\n"
                 : "=r"(r0), "=r"(r1), "=r"(r2), "=r"(r3) : "r"(addr));
}
__device__ __forceinline__ void ldsm_x4_t(u32& r0, u32& r1, u32& r2, u32& r3, u32 addr) {
    asm volatile("ldmatrix.sync.aligned.m8n8.x4.trans.shared.b16 {%0,%1,%2,%3},[%4];\n"
                 : "=r"(r0), "=r"(r1), "=r"(r2), "=r"(r3) : "r"(addr));
}
__device__ __forceinline__ void mma_f16(float* c, const u32* a, u32 b0, u32 b1) {
    asm volatile(
        "mma.sync.aligned.m16n8k16.row.col.f32.f16.f16.f32 "
        "{%0,%1,%2,%3},{%4,%5,%6,%7},{%8,%9},{%0,%1,%2,%3};\n"
        : "+f"(c[0]), "+f"(c[1]), "+f"(c[2]), "+f"(c[3])
        : "r"(a[0]), "r"(a[1]), "r"(a[2]), "r"(a[3]), "r"(b0), "r"(b1));
}
__device__ __forceinline__ void mma_f16_s(float* c, u32 a0, u32 a1, u32 a2, u32 a3,
                                          u32 b0, u32 b1) {
    asm volatile(
        "mma.sync.aligned.m16n8k16.row.col.f32.f16.f16.f32 "
        "{%0,%1,%2,%3},{%4,%5,%6,%7},{%8,%9},{%0,%1,%2,%3};\n"
        : "+f"(c[0]), "+f"(c[1]), "+f"(c[2]), "+f"(c[3])
        : "r"(a0), "r"(a1), "r"(a2), "r"(a3), "r"(b0), "r"(b1));
}
__device__ __forceinline__ void cp_async16(u32 dst, const void* src) {
    asm volatile("cp.async.cg.shared.global [%0],[%1],16;\n" :: "r"(dst), "l"(src));
}
__device__ __forceinline__ void cp_commit() {
    asm volatile("cp.async.commit_group;\n");
}
__device__ __forceinline__ void cp_wait1() {
    asm volatile("cp.async.wait_group 1;\n");
}
__device__ __forceinline__ void cp_wait0() {
    asm volatile("cp.async.wait_group 0;\n");
}

__device__ __forceinline__ void hg_load_tile(
    const f16* A, const f16* B, f16* As_s, f16* Bs_s,
    int k0, int bm, int bn, int K, int N,
    int a_ld_row, int a_ld_col, int b_ld_row, int b_ld_col) {
    u32 d0 = (u32)__cvta_generic_to_shared(As_s + a_ld_row * APITCH + a_ld_col);
    cp_async16(d0, A + (size_t)(bm * 128 + a_ld_row) * K + k0 + a_ld_col);
    u32 d1 = (u32)__cvta_generic_to_shared(As_s + (a_ld_row + 64) * APITCH + a_ld_col);
    cp_async16(d1, A + (size_t)(bm * 128 + a_ld_row + 64) * K + k0 + a_ld_col);
    u32 d2 = (u32)__cvta_generic_to_shared(Bs_s + b_ld_row * BPITCH + b_ld_col);
    cp_async16(d2, B + (size_t)(k0 + b_ld_row) * N + bn * 128 + b_ld_col);
    u32 d3 = (u32)__cvta_generic_to_shared(Bs_s + (b_ld_row + 16) * BPITCH + b_ld_col);
    cp_async16(d3, B + (size_t)(k0 + b_ld_row + 16) * N + bn * 128 + b_ld_col);
}

template <int EPI, int OUTMODE>
__global__ __launch_bounds__(256) void hgemm_kernel(
    const f16* __restrict__ A, const f16* __restrict__ B,
    const float* __restrict__ bias, const float* __restrict__ res,
    void* __restrict__ Cout, int M, int N, int K) {
    __shared__ f16 As[2 * 128 * APITCH];
    __shared__ f16 Bs[2 * 32 * BPITCH];

    int tid = threadIdx.x;
    int bm = blockIdx.y;
    int bn = blockIdx.x;
    int lane = tid & 31;
    int warp = tid >> 5;
    int wm = warp >> 1;
    int wn = warp & 1;

    int a_ld_row = tid >> 2;
    int a_ld_col = (tid & 3) * 8;
    int b_ld_row = tid >> 4;
    int b_ld_col = (tid & 15) * 8;

    float acc[2][8][4];
#pragma unroll
    for (int mi = 0; mi < 2; mi++) {
#pragma unroll
        for (int nj = 0; nj < 8; nj++) {
#pragma unroll
            for (int e = 0; e < 4; e++) acc[mi][nj][e] = 0.f;
        }
    }

    int KT = K / 32;

    hg_load_tile(A, B, As, Bs, 0, bm, bn, K, N,
                 a_ld_row, a_ld_col, b_ld_row, b_ld_col);
    cp_commit();

    int a_row = wm * 32 + (lane & 15);
    int a_csel = (lane >> 4) * 8;
    int b_row = (lane & 15);
    int b_csel = wn * 64 + (lane >> 4) * 8;

    for (int kt = 0; kt < KT; kt++) {
        int s = kt & 1;
        if (kt + 1 < KT) {
            int s2 = s ^ 1;
            hg_load_tile(A, B, As + s2 * 128 * APITCH, Bs + s2 * 32 * BPITCH,
                         (kt + 1) * 32, bm, bn, K, N,
                         a_ld_row, a_ld_col, b_ld_row, b_ld_col);
            cp_commit();
            cp_wait1();
        } else {
            cp_wait0();
        }
        __syncthreads();

        f16* As_s = As + s * 128 * APITCH;
        f16* Bs_s = Bs + s * 32 * BPITCH;

#pragma unroll
        for (int kk = 0; kk < 2; kk++) {
            u32 a_frag[2][4];
            u32 b_frag[4][4];
#pragma unroll
            for (int mi = 0; mi < 2; mi++) {
                u32 addr = (u32)__cvta_generic_to_shared(
                    As_s + (a_row + mi * 16) * APITCH + kk * 16 + a_csel);
                ldsm_x4(a_frag[mi][0], a_frag[mi][1], a_frag[mi][2], a_frag[mi][3], addr);
            }
#pragma unroll
            for (int nj = 0; nj < 4; nj++) {
                u32 addr = (u32)__cvta_generic_to_shared(
                    Bs_s + (kk * 16 + b_row) * BPITCH + nj * 16 + b_csel);
                ldsm_x4_t(b_frag[nj][0], b_frag[nj][1], b_frag[nj][2], b_frag[nj][3], addr);
            }
#pragma unroll
            for (int mi = 0; mi < 2; mi++) {
#pragma unroll
                for (int nj = 0; nj < 4; nj++) {
                    mma_f16(acc[mi][2 * nj],     a_frag[mi], b_frag[nj][0], b_frag[nj][1]);
                    mma_f16(acc[mi][2 * nj + 1], a_frag[mi], b_frag[nj][2], b_frag[nj][3]);
                }
            }
        }
        __syncthreads();
    }

    int gID = lane >> 2;
    int tig = lane & 3;
#pragma unroll
    for (int mi = 0; mi < 2; mi++) {
        int row0 = bm * 128 + wm * 32 + mi * 16 + gID;
#pragma unroll
        for (int nj = 0; nj < 8; nj++) {
            int col = bn * 128 + wn * 64 + nj * 8 + tig * 2;
            float v0 = acc[mi][nj][0];
            float v1 = acc[mi][nj][1];
            float v2 = acc[mi][nj][2];
            float v3 = acc[mi][nj][3];
            if (bias != 0) {
                float b0 = bias[col];
                float b1 = bias[col + 1];
                v0 += b0; v1 += b1; v2 += b0; v3 += b1;
            }
            if (EPI == EPI_GELU) {
                v0 = 0.5f * v0 * (1.0f + erff(v0 * 0.70710678118654752f));
                v1 = 0.5f * v1 * (1.0f + erff(v1 * 0.70710678118654752f));
                v2 = 0.5f * v2 * (1.0f + erff(v2 * 0.70710678118654752f));
                v3 = 0.5f * v3 * (1.0f + erff(v3 * 0.70710678118654752f));
            }
            if (EPI == EPI_RES) {
                v0 += res[(size_t)row0 * N + col];
                v1 += res[(size_t)row0 * N + col + 1];
                v2 += res[(size_t)(row0 + 8) * N + col];
                v3 += res[(size_t)(row0 + 8) * N + col + 1];
            }
            if (OUTMODE == 2) {
                f16* C = (f16*)Cout;
                *(__half2*)(C + (size_t)row0 * N + col) = __floats2half2_rn(v0, v1);
                *(__half2*)(C + (size_t)(row0 + 8) * N + col) = __floats2half2_rn(v2, v3);
            } else {
                float* C = (float*)Cout;
                C[(size_t)row0 * N + col] = v0;
                C[(size_t)row0 * N + col + 1] = v1;
                C[(size_t)(row0 + 8) * N + col] = v2;
                C[(size_t)(row0 + 8) * N + col + 1] = v3;
            }
        }
    }
}

// ---------------------------------------------------------------------------
// Flash attention: block = 128 q-rows x 1 head, 8 warps x 16 rows.
// Online softmax in registers; P repacked from C-fragments to A-fragments.
// smem: Q[128][72] + K[64][72] + V[64][72] fp16 = 36864 B.
// ---------------------------------------------------------------------------
#define FAPITCH 72

__global__ __launch_bounds__(256) void fattn_kernel(
    const f16* __restrict__ q, const f16* __restrict__ k,
    const f16* __restrict__ v, const int* __restrict__ cu,
    f16* __restrict__ outp, int ldqkv) {
    __shared__ f16 Qs[128 * FAPITCH];
    __shared__ f16 Ks[64 * FAPITCH];
    __shared__ f16 Vs[64 * FAPITCH];

    int h = blockIdx.y;
    int q0 = blockIdx.x * 128;

    int g = 0;
    for (int i = 0; i < NSEG; i++) {
        if (cu[i] <= q0) g = i;
    }
    int s0 = cu[g];
    int s1 = cu[g + 1];
    int len = s1 - s0;
    if (len > 512) len = 512;
    int nchunks = (len + 63) >> 6;

    int tid = threadIdx.x;
    int lane = tid & 31;
    int warp = tid >> 5;
    int gID = lane >> 2;
    int tig = lane & 3;
    int m0 = warp * 16;
    const float scale = 0.125f;

    // load Q tile 128x64
#pragma unroll
    for (int t = 0; t < 4; t++) {
        int gi = tid + t * 256;
        int i = gi >> 3;
        int c8 = (gi & 7) * 8;
        uint4 qv = *(const uint4*)(q + (size_t)(q0 + i) * ldqkv + h * HDIM + c8);
        *(uint4*)(Qs + i * FAPITCH + c8) = qv;
    }
    __syncthreads();

    u32 qa[4][4];
#pragma unroll
    for (int ks = 0; ks < 4; ks++) {
        u32 addr = (u32)__cvta_generic_to_shared(
            Qs + (m0 + (lane & 15)) * FAPITCH + ks * 16 + (lane >> 4) * 8);
        ldsm_x4(qa[ks][0], qa[ks][1], qa[ks][2], qa[ks][3], addr);
    }

    float mrun0 = -FLT_MAX, mrun1 = -FLT_MAX;
    float lrun0 = 0.f, lrun1 = 0.f;
    float acco[8][4];
#pragma unroll
    for (int nt = 0; nt < 8; nt++) {
#pragma unroll
        for (int e = 0; e < 4; e++) acco[nt][e] = 0.f;
    }

    for (int c = 0; c < nchunks; c++) {
        __syncthreads();
        // load K and V chunks (64x64 each)
#pragma unroll
        for (int t = 0; t < 2; t++) {
            int gi = tid + t * 256;
            int j = gi >> 3;
            int c8 = (gi & 7) * 8;
            int row = s0 + c * 64 + j;
            uint4 kv = make_uint4(0u, 0u, 0u, 0u);
            uint4 vv = make_uint4(0u, 0u, 0u, 0u);
            if (row < s1) {
                kv = *(const uint4*)(k + (size_t)row * ldqkv + h * HDIM + c8);
                vv = *(const uint4*)(v + (size_t)row * ldqkv + h * HDIM + c8);
            }
            *(uint4*)(Ks + j * FAPITCH + c8) = kv;
            *(uint4*)(Vs + j * FAPITCH + c8) = vv;
        }
        __syncthreads();

        // ---- S = Q K^T (16 x 64 per warp) ----
        float sacc[8][4];
#pragma unroll
        for (int nt = 0; nt < 8; nt++) {
#pragma unroll
            for (int e = 0; e < 4; e++) sacc[nt][e] = 0.f;
        }
#pragma unroll
        for (int ks = 0; ks < 4; ks++) {
#pragma unroll
            for (int ng = 0; ng < 4; ng++) {
                u32 r0, r1, r2, r3;
                u32 addr = (u32)__cvta_generic_to_shared(
                    Ks + (ng * 16 + (lane & 15)) * FAPITCH + ks * 16 + (lane >> 4) * 8);
                ldsm_x4(r0, r1, r2, r3, addr);
                mma_f16_s(sacc[ng * 2],     qa[ks][0], qa[ks][1], qa[ks][2], qa[ks][3], r0, r2);
                mma_f16_s(sacc[ng * 2 + 1], qa[ks][0], qa[ks][1], qa[ks][2], qa[ks][3], r1, r3);
            }
        }

        // ---- scale + tail mask ----
        bool tail = (c * 64 + 64 > len);
#pragma unroll
        for (int nt = 0; nt < 8; nt++) {
            sacc[nt][0] *= scale;
            sacc[nt][1] *= scale;
            sacc[nt][2] *= scale;
            sacc[nt][3] *= scale;
            if (tail) {
                int col = c * 64 + nt * 8 + tig * 2;
                if (col >= len)     { sacc[nt][0] = -FLT_MAX; sacc[nt][2] = -FLT_MAX; }
                if (col + 1 >= len) { sacc[nt][1] = -FLT_MAX; sacc[nt][3] = -FLT_MAX; }
            }
        }

        // ---- online softmax ----
        float mx0 = mrun0, mx1 = mrun1;
#pragma unroll
        for (int nt = 0; nt < 8; nt++) {
            mx0 = fmaxf(mx0, fmaxf(sacc[nt][0], sacc[nt][1]));
            mx1 = fmaxf(mx1, fmaxf(sacc[nt][2], sacc[nt][3]));
        }
        mx0 = fmaxf(mx0, __shfl_xor_sync(0xffffffff, mx0, 1));
        mx0 = fmaxf(mx0, __shfl_xor_sync(0xffffffff, mx0, 2));
        mx1 = fmaxf(mx1, __shfl_xor_sync(0xffffffff, mx1, 1));
        mx1 = fmaxf(mx1, __shfl_xor_sync(0xffffffff, mx1, 2));

        float alpha0 = __expf(mrun0 - mx0);
        float alpha1 = __expf(mrun1 - mx1);

        float p[8][4];
        float ps0 = 0.f, ps1 = 0.f;
#pragma unroll
        for (int nt = 0; nt < 8; nt++) {
            p[nt][0] = __expf(sacc[nt][0] - mx0);
            p[nt][1] = __expf(sacc[nt][1] - mx0);
            p[nt][2] = __expf(sacc[nt][2] - mx1);
            p[nt][3] = __expf(sacc[nt][3] - mx1);
            ps0 += p[nt][0] + p[nt][1];
            ps1 += p[nt][2] + p[nt][3];
        }
        ps0 += __shfl_xor_sync(0xffffffff, ps0, 1);
        ps0 += __shfl_xor_sync(0xffffffff, ps0, 2);
        ps1 += __shfl_xor_sync(0xffffffff, ps1, 1);
        ps1 += __shfl_xor_sync(0xffffffff, ps1, 2);

        lrun0 = lrun0 * alpha0 + ps0;
        lrun1 = lrun1 * alpha1 + ps1;
        mrun0 = mx0;
        mrun1 = mx1;

#pragma unroll
        for (int nt = 0; nt < 8; nt++) {
            acco[nt][0] *= alpha0;
            acco[nt][1] *= alpha0;
            acco[nt][2] *= alpha1;
            acco[nt][3] *= alpha1;
        }

        // ---- O += P V : pack P C-fragments into A-fragments ----
#pragma unroll
        for (int kk = 0; kk < 4; kk++) {
            __half2 h0 = __floats2half2_rn(p[2 * kk][0], p[2 * kk][1]);
            __half2 h1 = __floats2half2_rn(p[2 * kk][2], p[2 * kk][3]);
            __half2 h2 = __floats2half2_rn(p[2 * kk + 1][0], p[2 * kk + 1][1]);
            __half2 h3 = __floats2half2_rn(p[2 * kk + 1][2], p[2 * kk + 1][3]);
            u32 pa0 = *(u32*)&h0;
            u32 pa1 = *(u32*)&h1;
            u32 pa2 = *(u32*)&h2;
            u32 pa3 = *(u32*)&h3;
#pragma unroll
            for (int ng = 0; ng < 4; ng++) {
                u32 b0, b1, b2, b3;
                u32 vaddr = (u32)__cvta_generic_to_shared(
                    Vs + (kk * 16 + (lane & 15)) * FAPITCH + ng * 16 + (lane >> 4) * 8);
                ldsm_x4_t(b0, b1, b2, b3, vaddr);
                mma_f16_s(acco[ng * 2],     pa0, pa1, pa2, pa3, b0, b1);
                mma_f16_s(acco[ng * 2 + 1], pa0, pa1, pa2, pa3, b2, b3);
            }
        }
    }

    // ---- final normalize + write ----
    float inv0 = 1.0f / lrun0;
    float inv1 = 1.0f / lrun1;
    int orow0 = q0 + m0 + gID;
#pragma unroll
    for (int nt = 0; nt < 8; nt++) {
        int col = h * HDIM + nt * 8 + tig * 2;
        *(__half2*)(outp + (size_t)orow0 * DMODEL + col) =
            __floats2half2_rn(acco[nt][0] * inv0, acco[nt][1] * inv0);
        *(__half2*)(outp + (size_t)(orow0 + 8) * DMODEL + col) =
            __floats2half2_rn(acco[nt][2] * inv1, acco[nt][3] * inv1);
    }
}

// ---------------------------------------------------------------------------
// launch (single stream, round-10 structure)
// ---------------------------------------------------------------------------
extern "C" void kernel_launch(void* const* d_in, const int* in_sizes, int n_in,
                              void* d_out, int out_size) {
    const float* hidden = (const float*)d_in[0];
    const int*   cu     = (const int*)d_in[1];
    const float* Wq = (const float*)d_in[2];
    const float* bq = (const float*)d_in[3];
    const float* Wk = (const float*)d_in[4];
    const float* Wv = (const float*)d_in[5];
    const float* bv = (const float*)d_in[6];
    const float* Wo = (const float*)d_in[7];
    const float* bo = (const float*)d_in[8];
    const float* ln1_g = (const float*)d_in[9];
    const float* ln1_b = (const float*)d_in[10];
    const float* Wf1 = (const float*)d_in[11];
    const float* bf1 = (const float*)d_in[12];
    const float* Wf2 = (const float*)d_in[13];
    const float* bf2 = (const float*)d_in[14];
    const float* ln2_g = (const float*)d_in[15];
    const float* ln2_b = (const float*)d_in[16];
    float* out = (float*)d_out;

    float *hp, *bqkvp;
    f16 *qkvp, *xlnp, *attnp, *ylnp, *ffnp, *wqkvp, *wop, *wf1p, *wf2p;
    cudaGetSymbolAddress((void**)&qkvp,  g_qkv);
    cudaGetSymbolAddress((void**)&hp,    g_h);
    cudaGetSymbolAddress((void**)&bqkvp, g_bqkv);
    cudaGetSymbolAddress((void**)&xlnp,  g_xln);
    cudaGetSymbolAddress((void**)&attnp, g_attn);
    cudaGetSymbolAddress((void**)&ylnp,  g_yln);
    cudaGetSymbolAddress((void**)&ffnp,  g_ffn);
    cudaGetSymbolAddress((void**)&wqkvp, g_wqkv);
    cudaGetSymbolAddress((void**)&wop,   g_wo);
    cudaGetSymbolAddress((void**)&wf1p,  g_wf1);
    cudaGetSymbolAddress((void**)&wf2p,  g_wf2);

    dim3 blk(256);
    int nDD4 = DMODEL * DMODEL / 4;
    int nDF4 = DMODEL * FFN / 4;
    int c4 = DMODEL / 4;
    cvt_pack_kernel<<<(nDD4 + 255) / 256, blk>>>(Wq, wqkvp, c4, nDD4, D3, 0);
    cvt_pack_kernel<<<(nDD4 + 255) / 256, blk>>>(Wk, wqkvp, c4, nDD4, D3, DMODEL);
    cvt_pack_kernel<<<(nDD4 + 255) / 256, blk>>>(Wv, wqkvp, c4, nDD4, D3, 2 * DMODEL);
    pack_bias_kernel<<<(D3 + 255) / 256, blk>>>(bq, bv, bqkvp);
    cvt_kernel<<<(nDD4 + 255) / 256, blk>>>(Wo,  wop,  nDD4);
    cvt_kernel<<<(nDF4 + 255) / 256, blk>>>(Wf1, wf1p, nDF4);
    cvt_kernel<<<(nDF4 + 255) / 256, blk>>>(Wf2, wf2p, nDF4);

    dim3 gemmQKV(D3 / 128, SEQ / 128);
    dim3 gemmDD(DMODEL / 128, SEQ / 128);
    dim3 gemmDF(FFN / 128, SEQ / 128);

    ln_kernel<<<SEQ, blk>>>(hidden, ln1_g, ln1_b, xlnp);
    hgemm_kernel<EPI_BIAS, 2><<<gemmQKV, blk>>>(
        xlnp, wqkvp, bqkvp, 0, qkvp, SEQ, D3, DMODEL);
    fattn_kernel<<<dim3(SEQ / 128, NHEAD), blk>>>(
        qkvp, qkvp + DMODEL, qkvp + 2 * DMODEL, cu, attnp, D3);
    hgemm_kernel<EPI_RES, 0><<<gemmDD, blk>>>(
        attnp, wop, bo, hidden, hp, SEQ, DMODEL, DMODEL);
    ln_kernel<<<SEQ, blk>>>(hp, ln2_g, ln2_b, ylnp);
    hgemm_kernel<EPI_GELU, 2><<<gemmDF, blk>>>(
        ylnp, wf1p, bf1, 0, ffnp, SEQ, FFN, DMODEL);
    hgemm_kernel<EPI_RES, 0><<<gemmDD, blk>>>(
        ffnp, wf2p, bf2, hp, out, SEQ, DMODEL, FFN);
}

// round 16
// speedup vs baseline: 1.2335x; 1.0152x over previous
#include <cuda_runtime.h>
#include <cuda_fp16.h>
#include <cstdint>
#include <math.h>
#include <float.h>

#define SEQ 4096
#define DMODEL 1280
#define NHEAD 20
#define HDIM 64
#define FFN 5120
#define NSEG 8
#define LN_EPS 1e-5f
#define D3 (3 * DMODEL)

typedef unsigned int u32;
typedef __half f16;

// ---------------------------------------------------------------------------
// Scratch (device globals; no runtime allocation allowed)
// ---------------------------------------------------------------------------
__device__ f16   g_qkv[SEQ * D3];
__device__ float g_h[SEQ * DMODEL];
__device__ f16   g_xln[SEQ * DMODEL];
__device__ f16   g_attn[SEQ * DMODEL];
__device__ f16   g_yln[SEQ * DMODEL];
__device__ f16   g_ffn[SEQ * FFN];
__device__ f16   g_wqkv[DMODEL * D3];
__device__ float g_bqkv[D3];
__device__ f16   g_wo[DMODEL * DMODEL];
__device__ f16   g_wf1[DMODEL * FFN];
__device__ f16   g_wf2[FFN * DMODEL];

// ---------------------------------------------------------------------------
// fused weight convert: all 6 weights in one launch.
// segments (vec4 counts): Wq,Wk,Wv (pack into wqkv), Wo, Wf1, Wf2 (flat)
// ---------------------------------------------------------------------------
#define NDD4 (DMODEL * DMODEL / 4)
#define NDF4 (DMODEL * FFN / 4)
#define CVT_TOT (4 * NDD4 + 2 * NDF4)

__global__ __launch_bounds__(256) void cvt_all_kernel(
    const float* __restrict__ Wq, const float* __restrict__ Wk,
    const float* __restrict__ Wv, const float* __restrict__ Wo,
    const float* __restrict__ Wf1, const float* __restrict__ Wf2,
    f16* __restrict__ wqkv, f16* __restrict__ wo,
    f16* __restrict__ wf1, f16* __restrict__ wf2) {
    int idx = blockIdx.x * 256 + threadIdx.x;
    if (idx >= CVT_TOT) return;
    const int c4 = DMODEL / 4;

    const float* src;
    f16* dstp;
    int i;
    if (idx < 3 * NDD4) {
        int seg = idx / NDD4;          // 0,1,2
        i = idx - seg * NDD4;
        src = (seg == 0) ? Wq : (seg == 1) ? Wk : Wv;
        int row = i / c4;
        int col = (i - row * c4) * 4;
        dstp = wqkv + (size_t)row * D3 + seg * DMODEL + col;
    } else if (idx < 4 * NDD4) {
        i = idx - 3 * NDD4;
        src = Wo;
        dstp = wo + (size_t)i * 4;
    } else if (idx < 4 * NDD4 + NDF4) {
        i = idx - 4 * NDD4;
        src = Wf1;
        dstp = wf1 + (size_t)i * 4;
    } else {
        i = idx - 4 * NDD4 - NDF4;
        src = Wf2;
        dstp = wf2 + (size_t)i * 4;
    }
    float4 v = *(const float4*)(src + (size_t)i * 4);
    __half2* dp = (__half2*)dstp;
    dp[0] = __floats2half2_rn(v.x, v.y);
    dp[1] = __floats2half2_rn(v.z, v.w);
}

// pack QKV bias: [bq | 0 | bv] (fp32)
__global__ __launch_bounds__(256) void pack_bias_kernel(const float* __restrict__ bq,
                                                        const float* __restrict__ bv,
                                                        float* __restrict__ dst) {
    int i = blockIdx.x * 256 + threadIdx.x;
    if (i < D3) {
        float v = 0.f;
        if (i < DMODEL) v = bq[i];
        else if (i >= 2 * DMODEL) v = bv[i - 2 * DMODEL];
        dst[i] = v;
    }
}

// ---------------------------------------------------------------------------
// LayerNorm -> fp16 output
// ---------------------------------------------------------------------------
__global__ __launch_bounds__(256) void ln_kernel(const float* __restrict__ x,
                                                 const float* __restrict__ gam,
                                                 const float* __restrict__ bet,
                                                 f16* __restrict__ outp) {
    int r = blockIdx.x;
    const float* xr = x + (size_t)r * DMODEL;
    f16* outr = outp + (size_t)r * DMODEL;
    int tid = threadIdx.x;

    float s = 0.f, s2 = 0.f;
    for (int i = tid; i < DMODEL; i += 256) {
        float v = xr[i];
        s += v;
        s2 += v * v;
    }
    for (int off = 16; off > 0; off >>= 1) {
        s  += __shfl_xor_sync(0xffffffff, s, off);
        s2 += __shfl_xor_sync(0xffffffff, s2, off);
    }
    __shared__ float ss[8];
    __shared__ float ss2[8];
    int wid = tid >> 5;
    int lane = tid & 31;
    if (lane == 0) { ss[wid] = s; ss2[wid] = s2; }
    __syncthreads();
    if (wid == 0) {
        s  = (lane < 8) ? ss[lane]  : 0.f;
        s2 = (lane < 8) ? ss2[lane] : 0.f;
        for (int off = 4; off > 0; off >>= 1) {
            s  += __shfl_xor_sync(0xffffffff, s, off);
            s2 += __shfl_xor_sync(0xffffffff, s2, off);
        }
        if (lane == 0) { ss[0] = s; ss2[0] = s2; }
    }
    __syncthreads();
    float mu = ss[0] * (1.0f / DMODEL);
    float var = ss2[0] * (1.0f / DMODEL) - mu * mu;
    float inv = rsqrtf(var + LN_EPS);
    for (int i = tid; i < DMODEL; i += 256) {
        float v = (xr[i] - mu) * inv * gam[i] + bet[i];
        outr[i] = __float2half_rn(v);
    }
}

// ---------------------------------------------------------------------------
// fp16 tensor-core GEMM (round 10 config + forced 2 CTAs/SM):
// BM=128 BN=128 BK=32, 8 warps, warp tile 32x64, m16n8k16, 2-stage cp.async.
// OUTMODE: 0 = fp32, 2 = fp16
// ---------------------------------------------------------------------------
#define EPI_BIAS 0
#define EPI_GELU 1
#define EPI_RES  2

#define APITCH 40
#define BPITCH 136

__device__ __forceinline__ void ldsm_x4(u32& r0, u32& r1, u32& r2, u32& r3, u32 addr) {
    asm volatile("ldmatrix.sync.aligned.m8n8.x4.shared.b16 {%0,%1,%2,%3},[%4];\n"
                 : "=r"(r0), "=r"(r1), "=r"(r2), "=r"(r3) : "r"(addr));
}
__device__ __forceinline__ void ldsm_x4_t(u32& r0, u32& r1, u32& r2, u32& r3, u32 addr) {
    asm volatile("ldmatrix.sync.aligned.m8n8.x4.trans.shared.b16 {%0,%1,%2,%3},[%4];\n"
                 : "=r"(r0), "=r"(r1), "=r"(r2), "=r"(r3) : "r"(addr));
}
__device__ __forceinline__ void mma_f16(float* c, const u32* a, u32 b0, u32 b1) {
    asm volatile(
        "mma.sync.aligned.m16n8k16.row.col.f32.f16.f16.f32 "
        "{%0,%1,%2,%3},{%4,%5,%6,%7},{%8,%9},{%0,%1,%2,%3};\n"
        : "+f"(c[0]), "+f"(c[1]), "+f"(c[2]), "+f"(c[3])
        : "r"(a[0]), "r"(a[1]), "r"(a[2]), "r"(a[3]), "r"(b0), "r"(b1));
}
__device__ __forceinline__ void mma_f16_s(float* c, u32 a0, u32 a1, u32 a2, u32 a3,
                                          u32 b0, u32 b1) {
    asm volatile(
        "mma.sync.aligned.m16n8k16.row.col.f32.f16.f16.f32 "
        "{%0,%1,%2,%3},{%4,%5,%6,%7},{%8,%9},{%0,%1,%2,%3};\n"
        : "+f"(c[0]), "+f"(c[1]), "+f"(c[2]), "+f"(c[3])
        : "r"(a0), "r"(a1), "r"(a2), "r"(a3), "r"(b0), "r"(b1));
}
__device__ __forceinline__ void cp_async16(u32 dst, const void* src) {
    asm volatile("cp.async.cg.shared.global [%0],[%1],16;\n" :: "r"(dst), "l"(src));
}
__device__ __forceinline__ void cp_commit() {
    asm volatile("cp.async.commit_group;\n");
}
__device__ __forceinline__ void cp_wait1() {
    asm volatile("cp.async.wait_group 1;\n");
}
__device__ __forceinline__ void cp_wait0() {
    asm volatile("cp.async.wait_group 0;\n");
}

__device__ __forceinline__ void hg_load_tile(
    const f16* A, const f16* B, f16* As_s, f16* Bs_s,
    int k0, int bm, int bn, int K, int N,
    int a_ld_row, int a_ld_col, int b_ld_row, int b_ld_col) {
    u32 d0 = (u32)__cvta_generic_to_shared(As_s + a_ld_row * APITCH + a_ld_col);
    cp_async16(d0, A + (size_t)(bm * 128 + a_ld_row) * K + k0 + a_ld_col);
    u32 d1 = (u32)__cvta_generic_to_shared(As_s + (a_ld_row + 64) * APITCH + a_ld_col);
    cp_async16(d1, A + (size_t)(bm * 128 + a_ld_row + 64) * K + k0 + a_ld_col);
    u32 d2 = (u32)__cvta_generic_to_shared(Bs_s + b_ld_row * BPITCH + b_ld_col);
    cp_async16(d2, B + (size_t)(k0 + b_ld_row) * N + bn * 128 + b_ld_col);
    u32 d3 = (u32)__cvta_generic_to_shared(Bs_s + (b_ld_row + 16) * BPITCH + b_ld_col);
    cp_async16(d3, B + (size_t)(k0 + b_ld_row + 16) * N + bn * 128 + b_ld_col);
}

template <int EPI, int OUTMODE>
__global__ __launch_bounds__(256, 2) void hgemm_kernel(
    const f16* __restrict__ A, const f16* __restrict__ B,
    const float* __restrict__ bias, const float* __restrict__ res,
    void* __restrict__ Cout, int M, int N, int K) {
    __shared__ f16 As[2 * 128 * APITCH];
    __shared__ f16 Bs[2 * 32 * BPITCH];

    int tid = threadIdx.x;
    int bm = blockIdx.y;
    int bn = blockIdx.x;
    int lane = tid & 31;
    int warp = tid >> 5;
    int wm = warp >> 1;
    int wn = warp & 1;

    int a_ld_row = tid >> 2;
    int a_ld_col = (tid & 3) * 8;
    int b_ld_row = tid >> 4;
    int b_ld_col = (tid & 15) * 8;

    float acc[2][8][4];
#pragma unroll
    for (int mi = 0; mi < 2; mi++) {
#pragma unroll
        for (int nj = 0; nj < 8; nj++) {
#pragma unroll
            for (int e = 0; e < 4; e++) acc[mi][nj][e] = 0.f;
        }
    }

    int KT = K / 32;

    hg_load_tile(A, B, As, Bs, 0, bm, bn, K, N,
                 a_ld_row, a_ld_col, b_ld_row, b_ld_col);
    cp_commit();

    int a_row = wm * 32 + (lane & 15);
    int a_csel = (lane >> 4) * 8;
    int b_row = (lane & 15);
    int b_csel = wn * 64 + (lane >> 4) * 8;

    for (int kt = 0; kt < KT; kt++) {
        int s = kt & 1;
        if (kt + 1 < KT) {
            int s2 = s ^ 1;
            hg_load_tile(A, B, As + s2 * 128 * APITCH, Bs + s2 * 32 * BPITCH,
                         (kt + 1) * 32, bm, bn, K, N,
                         a_ld_row, a_ld_col, b_ld_row, b_ld_col);
            cp_commit();
            cp_wait1();
        } else {
            cp_wait0();
        }
        __syncthreads();

        f16* As_s = As + s * 128 * APITCH;
        f16* Bs_s = Bs + s * 32 * BPITCH;

#pragma unroll
        for (int kk = 0; kk < 2; kk++) {
            u32 a_frag[2][4];
            u32 b_frag[4][4];
#pragma unroll
            for (int mi = 0; mi < 2; mi++) {
                u32 addr = (u32)__cvta_generic_to_shared(
                    As_s + (a_row + mi * 16) * APITCH + kk * 16 + a_csel);
                ldsm_x4(a_frag[mi][0], a_frag[mi][1], a_frag[mi][2], a_frag[mi][3], addr);
            }
#pragma unroll
            for (int nj = 0; nj < 4; nj++) {
                u32 addr = (u32)__cvta_generic_to_shared(
                    Bs_s + (kk * 16 + b_row) * BPITCH + nj * 16 + b_csel);
                ldsm_x4_t(b_frag[nj][0], b_frag[nj][1], b_frag[nj][2], b_frag[nj][3], addr);
            }
#pragma unroll
            for (int mi = 0; mi < 2; mi++) {
#pragma unroll
                for (int nj = 0; nj < 4; nj++) {
                    mma_f16(acc[mi][2 * nj],     a_frag[mi], b_frag[nj][0], b_frag[nj][1]);
                    mma_f16(acc[mi][2 * nj + 1], a_frag[mi], b_frag[nj][2], b_frag[nj][3]);
                }
            }
        }
        __syncthreads();
    }

    int gID = lane >> 2;
    int tig = lane & 3;
#pragma unroll
    for (int mi = 0; mi < 2; mi++) {
        int row0 = bm * 128 + wm * 32 + mi * 16 + gID;
#pragma unroll
        for (int nj = 0; nj < 8; nj++) {
            int col = bn * 128 + wn * 64 + nj * 8 + tig * 2;
            float v0 = acc[mi][nj][0];
            float v1 = acc[mi][nj][1];
            float v2 = acc[mi][nj][2];
            float v3 = acc[mi][nj][3];
            if (bias != 0) {
                float b0 = bias[col];
                float b1 = bias[col + 1];
                v0 += b0; v1 += b1; v2 += b0; v3 += b1;
            }
            if (EPI == EPI_GELU) {
                v0 = 0.5f * v0 * (1.0f + erff(v0 * 0.70710678118654752f));
                v1 = 0.5f * v1 * (1.0f + erff(v1 * 0.70710678118654752f));
                v2 = 0.5f * v2 * (1.0f + erff(v2 * 0.70710678118654752f));
                v3 = 0.5f * v3 * (1.0f + erff(v3 * 0.70710678118654752f));
            }
            if (EPI == EPI_RES) {
                v0 += res[(size_t)row0 * N + col];
                v1 += res[(size_t)row0 * N + col + 1];
                v2 += res[(size_t)(row0 + 8) * N + col];
                v3 += res[(size_t)(row0 + 8) * N + col + 1];
            }
            if (OUTMODE == 2) {
                f16* C = (f16*)Cout;
                *(__half2*)(C + (size_t)row0 * N + col) = __floats2half2_rn(v0, v1);
                *(__half2*)(C + (size_t)(row0 + 8) * N + col) = __floats2half2_rn(v2, v3);
            } else {
                float* C = (float*)Cout;
                C[(size_t)row0 * N + col] = v0;
                C[(size_t)row0 * N + col + 1] = v1;
                C[(size_t)(row0 + 8) * N + col] = v2;
                C[(size_t)(row0 + 8) * N + col + 1] = v3;
            }
        }
    }
}

// ---------------------------------------------------------------------------
// Flash attention (verified round 14): block = 128 q-rows x 1 head,
// 8 warps x 16 rows, online softmax in registers.
// ---------------------------------------------------------------------------
#define FAPITCH 72

__global__ __launch_bounds__(256) void fattn_kernel(
    const f16* __restrict__ q, const f16* __restrict__ k,
    const f16* __restrict__ v, const int* __restrict__ cu,
    f16* __restrict__ outp, int ldqkv) {
    __shared__ f16 Qs[128 * FAPITCH];
    __shared__ f16 Ks[64 * FAPITCH];
    __shared__ f16 Vs[64 * FAPITCH];

    int h = blockIdx.y;
    int q0 = blockIdx.x * 128;

    int g = 0;
    for (int i = 0; i < NSEG; i++) {
        if (cu[i] <= q0) g = i;
    }
    int s0 = cu[g];
    int s1 = cu[g + 1];
    int len = s1 - s0;
    if (len > 512) len = 512;
    int nchunks = (len + 63) >> 6;

    int tid = threadIdx.x;
    int lane = tid & 31;
    int warp = tid >> 5;
    int gID = lane >> 2;
    int tig = lane & 3;
    int m0 = warp * 16;
    const float scale = 0.125f;

#pragma unroll
    for (int t = 0; t < 4; t++) {
        int gi = tid + t * 256;
        int i = gi >> 3;
        int c8 = (gi & 7) * 8;
        uint4 qv = *(const uint4*)(q + (size_t)(q0 + i) * ldqkv + h * HDIM + c8);
        *(uint4*)(Qs + i * FAPITCH + c8) = qv;
    }
    __syncthreads();

    u32 qa[4][4];
#pragma unroll
    for (int ks = 0; ks < 4; ks++) {
        u32 addr = (u32)__cvta_generic_to_shared(
            Qs + (m0 + (lane & 15)) * FAPITCH + ks * 16 + (lane >> 4) * 8);
        ldsm_x4(qa[ks][0], qa[ks][1], qa[ks][2], qa[ks][3], addr);
    }

    float mrun0 = -FLT_MAX, mrun1 = -FLT_MAX;
    float lrun0 = 0.f, lrun1 = 0.f;
    float acco[8][4];
#pragma unroll
    for (int nt = 0; nt < 8; nt++) {
#pragma unroll
        for (int e = 0; e < 4; e++) acco[nt][e] = 0.f;
    }

    for (int c = 0; c < nchunks; c++) {
        __syncthreads();
#pragma unroll
        for (int t = 0; t < 2; t++) {
            int gi = tid + t * 256;
            int j = gi >> 3;
            int c8 = (gi & 7) * 8;
            int row = s0 + c * 64 + j;
            uint4 kv = make_uint4(0u, 0u, 0u, 0u);
            uint4 vv = make_uint4(0u, 0u, 0u, 0u);
            if (row < s1) {
                kv = *(const uint4*)(k + (size_t)row * ldqkv + h * HDIM + c8);
                vv = *(const uint4*)(v + (size_t)row * ldqkv + h * HDIM + c8);
            }
            *(uint4*)(Ks + j * FAPITCH + c8) = kv;
            *(uint4*)(Vs + j * FAPITCH + c8) = vv;
        }
        __syncthreads();

        float sacc[8][4];
#pragma unroll
        for (int nt = 0; nt < 8; nt++) {
#pragma unroll
            for (int e = 0; e < 4; e++) sacc[nt][e] = 0.f;
        }
#pragma unroll
        for (int ks = 0; ks < 4; ks++) {
#pragma unroll
            for (int ng = 0; ng < 4; ng++) {
                u32 r0, r1, r2, r3;
                u32 addr = (u32)__cvta_generic_to_shared(
                    Ks + (ng * 16 + (lane & 15)) * FAPITCH + ks * 16 + (lane >> 4) * 8);
                ldsm_x4(r0, r1, r2, r3, addr);
                mma_f16_s(sacc[ng * 2],     qa[ks][0], qa[ks][1], qa[ks][2], qa[ks][3], r0, r2);
                mma_f16_s(sacc[ng * 2 + 1], qa[ks][0], qa[ks][1], qa[ks][2], qa[ks][3], r1, r3);
            }
        }

        bool tail = (c * 64 + 64 > len);
#pragma unroll
        for (int nt = 0; nt < 8; nt++) {
            sacc[nt][0] *= scale;
            sacc[nt][1] *= scale;
            sacc[nt][2] *= scale;
            sacc[nt][3] *= scale;
            if (tail) {
                int col = c * 64 + nt * 8 + tig * 2;
                if (col >= len)     { sacc[nt][0] = -FLT_MAX; sacc[nt][2] = -FLT_MAX; }
                if (col + 1 >= len) { sacc[nt][1] = -FLT_MAX; sacc[nt][3] = -FLT_MAX; }
            }
        }

        float mx0 = mrun0, mx1 = mrun1;
#pragma unroll
        for (int nt = 0; nt < 8; nt++) {
            mx0 = fmaxf(mx0, fmaxf(sacc[nt][0], sacc[nt][1]));
            mx1 = fmaxf(mx1, fmaxf(sacc[nt][2], sacc[nt][3]));
        }
        mx0 = fmaxf(mx0, __shfl_xor_sync(0xffffffff, mx0, 1));
        mx0 = fmaxf(mx0, __shfl_xor_sync(0xffffffff, mx0, 2));
        mx1 = fmaxf(mx1, __shfl_xor_sync(0xffffffff, mx1, 1));
        mx1 = fmaxf(mx1, __shfl_xor_sync(0xffffffff, mx1, 2));

        float alpha0 = __expf(mrun0 - mx0);
        float alpha1 = __expf(mrun1 - mx1);

        float p[8][4];
        float ps0 = 0.f, ps1 = 0.f;
#pragma unroll
        for (int nt = 0; nt < 8; nt++) {
            p[nt][0] = __expf(sacc[nt][0] - mx0);
            p[nt][1] = __expf(sacc[nt][1] - mx0);
            p[nt][2] = __expf(sacc[nt][2] - mx1);
            p[nt][3] = __expf(sacc[nt][3] - mx1);
            ps0 += p[nt][0] + p[nt][1];
            ps1 += p[nt][2] + p[nt][3];
        }
        ps0 += __shfl_xor_sync(0xffffffff, ps0, 1);
        ps0 += __shfl_xor_sync(0xffffffff, ps0, 2);
        ps1 += __shfl_xor_sync(0xffffffff, ps1, 1);
        ps1 += __shfl_xor_sync(0xffffffff, ps1, 2);

        lrun0 = lrun0 * alpha0 + ps0;
        lrun1 = lrun1 * alpha1 + ps1;
        mrun0 = mx0;
        mrun1 = mx1;

#pragma unroll
        for (int nt = 0; nt < 8; nt++) {
            acco[nt][0] *= alpha0;
            acco[nt][1] *= alpha0;
            acco[nt][2] *= alpha1;
            acco[nt][3] *= alpha1;
        }

#pragma unroll
        for (int kk = 0; kk < 4; kk++) {
            __half2 h0 = __floats2half2_rn(p[2 * kk][0], p[2 * kk][1]);
            __half2 h1 = __floats2half2_rn(p[2 * kk][2], p[2 * kk][3]);
            __half2 h2 = __floats2half2_rn(p[2 * kk + 1][0], p[2 * kk + 1][1]);
            __half2 h3 = __floats2half2_rn(p[2 * kk + 1][2], p[2 * kk + 1][3]);
            u32 pa0 = *(u32*)&h0;
            u32 pa1 = *(u32*)&h1;
            u32 pa2 = *(u32*)&h2;
            u32 pa3 = *(u32*)&h3;
#pragma unroll
            for (int ng = 0; ng < 4; ng++) {
                u32 b0, b1, b2, b3;
                u32 vaddr = (u32)__cvta_generic_to_shared(
                    Vs + (kk * 16 + (lane & 15)) * FAPITCH + ng * 16 + (lane >> 4) * 8);
                ldsm_x4_t(b0, b1, b2, b3, vaddr);
                mma_f16_s(acco[ng * 2],     pa0, pa1, pa2, pa3, b0, b1);
                mma_f16_s(acco[ng * 2 + 1], pa0, pa1, pa2, pa3, b2, b3);
            }
        }
    }

    float inv0 = 1.0f / lrun0;
    float inv1 = 1.0f / lrun1;
    int orow0 = q0 + m0 + gID;
#pragma unroll
    for (int nt = 0; nt < 8; nt++) {
        int col = h * HDIM + nt * 8 + tig * 2;
        *(__half2*)(outp + (size_t)orow0 * DMODEL + col) =
            __floats2half2_rn(acco[nt][0] * inv0, acco[nt][1] * inv0);
        *(__half2*)(outp + (size_t)(orow0 + 8) * DMODEL + col) =
            __floats2half2_rn(acco[nt][2] * inv1, acco[nt][3] * inv1);
    }
}

// ---------------------------------------------------------------------------
// launch (single stream)
// ---------------------------------------------------------------------------
extern "C" void kernel_launch(void* const* d_in, const int* in_sizes, int n_in,
                              void* d_out, int out_size) {
    const float* hidden = (const float*)d_in[0];
    const int*   cu     = (const int*)d_in[1];
    const float* Wq = (const float*)d_in[2];
    const float* bq = (const float*)d_in[3];
    const float* Wk = (const float*)d_in[4];
    const float* Wv = (const float*)d_in[5];
    const float* bv = (const float*)d_in[6];
    const float* Wo = (const float*)d_in[7];
    const float* bo = (const float*)d_in[8];
    const float* ln1_g = (const float*)d_in[9];
    const float* ln1_b = (const float*)d_in[10];
    const float* Wf1 = (const float*)d_in[11];
    const float* bf1 = (const float*)d_in[12];
    const float* Wf2 = (const float*)d_in[13];
    const float* bf2 = (const float*)d_in[14];
    const float* ln2_g = (const float*)d_in[15];
    const float* ln2_b = (const float*)d_in[16];
    float* out = (float*)d_out;

    float *hp, *bqkvp;
    f16 *qkvp, *xlnp, *attnp, *ylnp, *ffnp, *wqkvp, *wop, *wf1p, *wf2p;
    cudaGetSymbolAddress((void**)&qkvp,  g_qkv);
    cudaGetSymbolAddress((void**)&hp,    g_h);
    cudaGetSymbolAddress((void**)&bqkvp, g_bqkv);
    cudaGetSymbolAddress((void**)&xlnp,  g_xln);
    cudaGetSymbolAddress((void**)&attnp, g_attn);
    cudaGetSymbolAddress((void**)&ylnp,  g_yln);
    cudaGetSymbolAddress((void**)&ffnp,  g_ffn);
    cudaGetSymbolAddress((void**)&wqkvp, g_wqkv);
    cudaGetSymbolAddress((void**)&wop,   g_wo);
    cudaGetSymbolAddress((void**)&wf1p,  g_wf1);
    cudaGetSymbolAddress((void**)&wf2p,  g_wf2);

    dim3 blk(256);
    cvt_all_kernel<<<(CVT_TOT + 255) / 256, blk>>>(
        Wq, Wk, Wv, Wo, Wf1, Wf2, wqkvp, wop, wf1p, wf2p);
    pack_bias_kernel<<<(D3 + 255) / 256, blk>>>(bq, bv, bqkvp);

    dim3 gemmQKV(D3 / 128, SEQ / 128);
    dim3 gemmDD(DMODEL / 128, SEQ / 128);
    dim3 gemmDF(FFN / 128, SEQ / 128);

    ln_kernel<<<SEQ, blk>>>(hidden, ln1_g, ln1_b, xlnp);
    hgemm_kernel<EPI_BIAS, 2><<<gemmQKV, blk>>>(
        xlnp, wqkvp, bqkvp, 0, qkvp, SEQ, D3, DMODEL);
    fattn_kernel<<<dim3(SEQ / 128, NHEAD), blk>>>(
        qkvp, qkvp + DMODEL, qkvp + 2 * DMODEL, cu, attnp, D3);
    hgemm_kernel<EPI_RES, 0><<<gemmDD, blk>>>(
        attnp, wop, bo, hidden, hp, SEQ, DMODEL, DMODEL);
    ln_kernel<<<SEQ, blk>>>(hp, ln2_g, ln2_b, ylnp);
    hgemm_kernel<EPI_GELU, 2><<<gemmDF, blk>>>(
        ylnp, wf1p, bf1, 0, ffnp, SEQ, FFN, DMODEL);
    hgemm_kernel<EPI_RES, 0><<<gemmDD, blk>>>(
        ffnp, wf2p, bf2, hp, out, SEQ, DMODEL, FFN);
}

// round 17
// speedup vs baseline: 1.2582x; 1.0201x over previous
#include <cuda_runtime.h>
#include <cuda_fp16.h>
#include <cstdint>
#include <math.h>
#include <float.h>

#define SEQ 4096
#define DMODEL 1280
#define NHEAD 20
#define HDIM 64
#define FFN 5120
#define NSEG 8
#define LN_EPS 1e-5f
#define D3 (3 * DMODEL)

typedef unsigned int u32;
typedef __half f16;

// ---------------------------------------------------------------------------
// Scratch (device globals; no runtime allocation allowed)
// ---------------------------------------------------------------------------
__device__ f16   g_qkv[SEQ * D3];
__device__ float g_h[SEQ * DMODEL];
__device__ f16   g_xln[SEQ * DMODEL];
__device__ f16   g_attn[SEQ * DMODEL];
__device__ f16   g_yln[SEQ * DMODEL];
__device__ f16   g_ffn[SEQ * FFN];
__device__ f16   g_wqkv[DMODEL * D3];
__device__ float g_bqkv[D3];
__device__ f16   g_wo[DMODEL * DMODEL];
__device__ f16   g_wf1[DMODEL * FFN];
__device__ f16   g_wf2[FFN * DMODEL];

// ---------------------------------------------------------------------------
// fused weight convert: all 6 weights in one launch.
// ---------------------------------------------------------------------------
#define NDD4 (DMODEL * DMODEL / 4)
#define NDF4 (DMODEL * FFN / 4)
#define CVT_TOT (4 * NDD4 + 2 * NDF4)

__global__ __launch_bounds__(256) void cvt_all_kernel(
    const float* __restrict__ Wq, const float* __restrict__ Wk,
    const float* __restrict__ Wv, const float* __restrict__ Wo,
    const float* __restrict__ Wf1, const float* __restrict__ Wf2,
    f16* __restrict__ wqkv, f16* __restrict__ wo,
    f16* __restrict__ wf1, f16* __restrict__ wf2) {
    int idx = blockIdx.x * 256 + threadIdx.x;
    if (idx >= CVT_TOT) return;
    const int c4 = DMODEL / 4;

    const float* src;
    f16* dstp;
    int i;
    if (idx < 3 * NDD4) {
        int seg = idx / NDD4;
        i = idx - seg * NDD4;
        src = (seg == 0) ? Wq : (seg == 1) ? Wk : Wv;
        int row = i / c4;
        int col = (i - row * c4) * 4;
        dstp = wqkv + (size_t)row * D3 + seg * DMODEL + col;
    } else if (idx < 4 * NDD4) {
        i = idx - 3 * NDD4;
        src = Wo;
        dstp = wo + (size_t)i * 4;
    } else if (idx < 4 * NDD4 + NDF4) {
        i = idx - 4 * NDD4;
        src = Wf1;
        dstp = wf1 + (size_t)i * 4;
    } else {
        i = idx - 4 * NDD4 - NDF4;
        src = Wf2;
        dstp = wf2 + (size_t)i * 4;
    }
    float4 v = *(const float4*)(src + (size_t)i * 4);
    __half2* dp = (__half2*)dstp;
    dp[0] = __floats2half2_rn(v.x, v.y);
    dp[1] = __floats2half2_rn(v.z, v.w);
}

// pack QKV bias: [bq | 0 | bv] (fp32)
__global__ __launch_bounds__(256) void pack_bias_kernel(const float* __restrict__ bq,
                                                        const float* __restrict__ bv,
                                                        float* __restrict__ dst) {
    int i = blockIdx.x * 256 + threadIdx.x;
    if (i < D3) {
        float v = 0.f;
        if (i < DMODEL) v = bq[i];
        else if (i >= 2 * DMODEL) v = bv[i - 2 * DMODEL];
        dst[i] = v;
    }
}

// ---------------------------------------------------------------------------
// LayerNorm -> fp16 output
// ---------------------------------------------------------------------------
__global__ __launch_bounds__(256) void ln_kernel(const float* __restrict__ x,
                                                 const float* __restrict__ gam,
                                                 const float* __restrict__ bet,
                                                 f16* __restrict__ outp) {
    int r = blockIdx.x;
    const float* xr = x + (size_t)r * DMODEL;
    f16* outr = outp + (size_t)r * DMODEL;
    int tid = threadIdx.x;

    float s = 0.f, s2 = 0.f;
    for (int i = tid; i < DMODEL; i += 256) {
        float v = xr[i];
        s += v;
        s2 += v * v;
    }
    for (int off = 16; off > 0; off >>= 1) {
        s  += __shfl_xor_sync(0xffffffff, s, off);
        s2 += __shfl_xor_sync(0xffffffff, s2, off);
    }
    __shared__ float ss[8];
    __shared__ float ss2[8];
    int wid = tid >> 5;
    int lane = tid & 31;
    if (lane == 0) { ss[wid] = s; ss2[wid] = s2; }
    __syncthreads();
    if (wid == 0) {
        s  = (lane < 8) ? ss[lane]  : 0.f;
        s2 = (lane < 8) ? ss2[lane] : 0.f;
        for (int off = 4; off > 0; off >>= 1) {
            s  += __shfl_xor_sync(0xffffffff, s, off);
            s2 += __shfl_xor_sync(0xffffffff, s2, off);
        }
        if (lane == 0) { ss[0] = s; ss2[0] = s2; }
    }
    __syncthreads();
    float mu = ss[0] * (1.0f / DMODEL);
    float var = ss2[0] * (1.0f / DMODEL) - mu * mu;
    float inv = rsqrtf(var + LN_EPS);
    for (int i = tid; i < DMODEL; i += 256) {
        float v = (xr[i] - mu) * inv * gam[i] + bet[i];
        outr[i] = __float2half_rn(v);
    }
}

// ---------------------------------------------------------------------------
// common mma helpers
// ---------------------------------------------------------------------------
#define EPI_BIAS 0
#define EPI_GELU 1
#define EPI_RES  2

#define APITCH 40
#define BPITCH 136
#define BPITCH64 72

__device__ __forceinline__ void ldsm_x4(u32& r0, u32& r1, u32& r2, u32& r3, u32 addr) {
    asm volatile("ldmatrix.sync.aligned.m8n8.x4.shared.b16 {%0,%1,%2,%3},[%4];\n"
                 : "=r"(r0), "=r"(r1), "=r"(r2), "=r"(r3) : "r"(addr));
}
__device__ __forceinline__ void ldsm_x4_t(u32& r0, u32& r1, u32& r2, u32& r3, u32 addr) {
    asm volatile("ldmatrix.sync.aligned.m8n8.x4.trans.shared.b16 {%0,%1,%2,%3},[%4];\n"
                 : "=r"(r0), "=r"(r1), "=r"(r2), "=r"(r3) : "r"(addr));
}
__device__ __forceinline__ void mma_f16(float* c, const u32* a, u32 b0, u32 b1) {
    asm volatile(
        "mma.sync.aligned.m16n8k16.row.col.f32.f16.f16.f32 "
        "{%0,%1,%2,%3},{%4,%5,%6,%7},{%8,%9},{%0,%1,%2,%3};\n"
        : "+f"(c[0]), "+f"(c[1]), "+f"(c[2]), "+f"(c[3])
        : "r"(a[0]), "r"(a[1]), "r"(a[2]), "r"(a[3]), "r"(b0), "r"(b1));
}
__device__ __forceinline__ void mma_f16_s(float* c, u32 a0, u32 a1, u32 a2, u32 a3,
                                          u32 b0, u32 b1) {
    asm volatile(
        "mma.sync.aligned.m16n8k16.row.col.f32.f16.f16.f32 "
        "{%0,%1,%2,%3},{%4,%5,%6,%7},{%8,%9},{%0,%1,%2,%3};\n"
        : "+f"(c[0]), "+f"(c[1]), "+f"(c[2]), "+f"(c[3])
        : "r"(a0), "r"(a1), "r"(a2), "r"(a3), "r"(b0), "r"(b1));
}
__device__ __forceinline__ void cp_async16(u32 dst, const void* src) {
    asm volatile("cp.async.cg.shared.global [%0],[%1],16;\n" :: "r"(dst), "l"(src));
}
__device__ __forceinline__ void cp_commit() {
    asm volatile("cp.async.commit_group;\n");
}
__device__ __forceinline__ void cp_wait1() {
    asm volatile("cp.async.wait_group 1;\n");
}
__device__ __forceinline__ void cp_wait0() {
    asm volatile("cp.async.wait_group 0;\n");
}

// ---------------------------------------------------------------------------
// 128x128 GEMM (verified): BK=32, 8 warps, warp tile 32x64, 2 CTAs/SM.
// ---------------------------------------------------------------------------
__device__ __forceinline__ void hg_load_tile(
    const f16* A, const f16* B, f16* As_s, f16* Bs_s,
    int k0, int bm, int bn, int K, int N,
    int a_ld_row, int a_ld_col, int b_ld_row, int b_ld_col) {
    u32 d0 = (u32)__cvta_generic_to_shared(As_s + a_ld_row * APITCH + a_ld_col);
    cp_async16(d0, A + (size_t)(bm * 128 + a_ld_row) * K + k0 + a_ld_col);
    u32 d1 = (u32)__cvta_generic_to_shared(As_s + (a_ld_row + 64) * APITCH + a_ld_col);
    cp_async16(d1, A + (size_t)(bm * 128 + a_ld_row + 64) * K + k0 + a_ld_col);
    u32 d2 = (u32)__cvta_generic_to_shared(Bs_s + b_ld_row * BPITCH + b_ld_col);
    cp_async16(d2, B + (size_t)(k0 + b_ld_row) * N + bn * 128 + b_ld_col);
    u32 d3 = (u32)__cvta_generic_to_shared(Bs_s + (b_ld_row + 16) * BPITCH + b_ld_col);
    cp_async16(d3, B + (size_t)(k0 + b_ld_row + 16) * N + bn * 128 + b_ld_col);
}

template <int EPI, int OUTMODE>
__global__ __launch_bounds__(256, 2) void hgemm_kernel(
    const f16* __restrict__ A, const f16* __restrict__ B,
    const float* __restrict__ bias, const float* __restrict__ res,
    void* __restrict__ Cout, int M, int N, int K) {
    __shared__ f16 As[2 * 128 * APITCH];
    __shared__ f16 Bs[2 * 32 * BPITCH];

    int tid = threadIdx.x;
    int bm = blockIdx.y;
    int bn = blockIdx.x;
    int lane = tid & 31;
    int warp = tid >> 5;
    int wm = warp >> 1;
    int wn = warp & 1;

    int a_ld_row = tid >> 2;
    int a_ld_col = (tid & 3) * 8;
    int b_ld_row = tid >> 4;
    int b_ld_col = (tid & 15) * 8;

    float acc[2][8][4];
#pragma unroll
    for (int mi = 0; mi < 2; mi++) {
#pragma unroll
        for (int nj = 0; nj < 8; nj++) {
#pragma unroll
            for (int e = 0; e < 4; e++) acc[mi][nj][e] = 0.f;
        }
    }

    int KT = K / 32;

    hg_load_tile(A, B, As, Bs, 0, bm, bn, K, N,
                 a_ld_row, a_ld_col, b_ld_row, b_ld_col);
    cp_commit();

    int a_row = wm * 32 + (lane & 15);
    int a_csel = (lane >> 4) * 8;
    int b_row = (lane & 15);
    int b_csel = wn * 64 + (lane >> 4) * 8;

    for (int kt = 0; kt < KT; kt++) {
        int s = kt & 1;
        if (kt + 1 < KT) {
            int s2 = s ^ 1;
            hg_load_tile(A, B, As + s2 * 128 * APITCH, Bs + s2 * 32 * BPITCH,
                         (kt + 1) * 32, bm, bn, K, N,
                         a_ld_row, a_ld_col, b_ld_row, b_ld_col);
            cp_commit();
            cp_wait1();
        } else {
            cp_wait0();
        }
        __syncthreads();

        f16* As_s = As + s * 128 * APITCH;
        f16* Bs_s = Bs + s * 32 * BPITCH;

#pragma unroll
        for (int kk = 0; kk < 2; kk++) {
            u32 a_frag[2][4];
            u32 b_frag[4][4];
#pragma unroll
            for (int mi = 0; mi < 2; mi++) {
                u32 addr = (u32)__cvta_generic_to_shared(
                    As_s + (a_row + mi * 16) * APITCH + kk * 16 + a_csel);
                ldsm_x4(a_frag[mi][0], a_frag[mi][1], a_frag[mi][2], a_frag[mi][3], addr);
            }
#pragma unroll
            for (int nj = 0; nj < 4; nj++) {
                u32 addr = (u32)__cvta_generic_to_shared(
                    Bs_s + (kk * 16 + b_row) * BPITCH + nj * 16 + b_csel);
                ldsm_x4_t(b_frag[nj][0], b_frag[nj][1], b_frag[nj][2], b_frag[nj][3], addr);
            }
#pragma unroll
            for (int mi = 0; mi < 2; mi++) {
#pragma unroll
                for (int nj = 0; nj < 4; nj++) {
                    mma_f16(acc[mi][2 * nj],     a_frag[mi], b_frag[nj][0], b_frag[nj][1]);
                    mma_f16(acc[mi][2 * nj + 1], a_frag[mi], b_frag[nj][2], b_frag[nj][3]);
                }
            }
        }
        __syncthreads();
    }

    int gID = lane >> 2;
    int tig = lane & 3;
#pragma unroll
    for (int mi = 0; mi < 2; mi++) {
        int row0 = bm * 128 + wm * 32 + mi * 16 + gID;
#pragma unroll
        for (int nj = 0; nj < 8; nj++) {
            int col = bn * 128 + wn * 64 + nj * 8 + tig * 2;
            float v0 = acc[mi][nj][0];
            float v1 = acc[mi][nj][1];
            float v2 = acc[mi][nj][2];
            float v3 = acc[mi][nj][3];
            if (bias != 0) {
                float b0 = bias[col];
                float b1 = bias[col + 1];
                v0 += b0; v1 += b1; v2 += b0; v3 += b1;
            }
            if (EPI == EPI_GELU) {
                v0 = 0.5f * v0 * (1.0f + erff(v0 * 0.70710678118654752f));
                v1 = 0.5f * v1 * (1.0f + erff(v1 * 0.70710678118654752f));
                v2 = 0.5f * v2 * (1.0f + erff(v2 * 0.70710678118654752f));
                v3 = 0.5f * v3 * (1.0f + erff(v3 * 0.70710678118654752f));
            }
            if (EPI == EPI_RES) {
                v0 += res[(size_t)row0 * N + col];
                v1 += res[(size_t)row0 * N + col + 1];
                v2 += res[(size_t)(row0 + 8) * N + col];
                v3 += res[(size_t)(row0 + 8) * N + col + 1];
            }
            if (OUTMODE == 2) {
                f16* C = (f16*)Cout;
                *(__half2*)(C + (size_t)row0 * N + col) = __floats2half2_rn(v0, v1);
                *(__half2*)(C + (size_t)(row0 + 8) * N + col) = __floats2half2_rn(v2, v3);
            } else {
                float* C = (float*)Cout;
                C[(size_t)row0 * N + col] = v0;
                C[(size_t)row0 * N + col + 1] = v1;
                C[(size_t)(row0 + 8) * N + col] = v2;
                C[(size_t)(row0 + 8) * N + col + 1] = v3;
            }
        }
    }
}

// ---------------------------------------------------------------------------
// 128x64 GEMM: BK=32, 8 warps, warp tile 32x32, 3 CTAs/SM target.
// For the 320-block (N=1280) launches to cut wave quantization.
// ---------------------------------------------------------------------------
__device__ __forceinline__ void hg64_load_tile(
    const f16* A, const f16* B, f16* As_s, f16* Bs_s,
    int k0, int bm, int bn, int K, int N,
    int a_ld_row, int a_ld_col, int b_ld_row, int b_ld_col) {
    u32 d0 = (u32)__cvta_generic_to_shared(As_s + a_ld_row * APITCH + a_ld_col);
    cp_async16(d0, A + (size_t)(bm * 128 + a_ld_row) * K + k0 + a_ld_col);
    u32 d1 = (u32)__cvta_generic_to_shared(As_s + (a_ld_row + 64) * APITCH + a_ld_col);
    cp_async16(d1, A + (size_t)(bm * 128 + a_ld_row + 64) * K + k0 + a_ld_col);
    u32 d2 = (u32)__cvta_generic_to_shared(Bs_s + b_ld_row * BPITCH64 + b_ld_col);
    cp_async16(d2, B + (size_t)(k0 + b_ld_row) * N + bn * 64 + b_ld_col);
}

template <int EPI, int OUTMODE>
__global__ __launch_bounds__(256, 3) void hgemm64_kernel(
    const f16* __restrict__ A, const f16* __restrict__ B,
    const float* __restrict__ bias, const float* __restrict__ res,
    void* __restrict__ Cout, int M, int N, int K) {
    __shared__ f16 As[2 * 128 * APITCH];
    __shared__ f16 Bs[2 * 32 * BPITCH64];

    int tid = threadIdx.x;
    int bm = blockIdx.y;
    int bn = blockIdx.x;
    int lane = tid & 31;
    int warp = tid >> 5;
    int wm = warp >> 1;      // 0..3 -> 32-row tile
    int wn = warp & 1;       // 0..1 -> 32-col tile

    int a_ld_row = tid >> 2;        // 0..63
    int a_ld_col = (tid & 3) * 8;
    int b_ld_row = tid >> 3;        // 0..31
    int b_ld_col = (tid & 7) * 8;

    float acc[2][4][4];
#pragma unroll
    for (int mi = 0; mi < 2; mi++) {
#pragma unroll
        for (int nj = 0; nj < 4; nj++) {
#pragma unroll
            for (int e = 0; e < 4; e++) acc[mi][nj][e] = 0.f;
        }
    }

    int KT = K / 32;

    hg64_load_tile(A, B, As, Bs, 0, bm, bn, K, N,
                   a_ld_row, a_ld_col, b_ld_row, b_ld_col);
    cp_commit();

    int a_row = wm * 32 + (lane & 15);
    int a_csel = (lane >> 4) * 8;
    int b_row = (lane & 15);
    int b_csel = wn * 32 + (lane >> 4) * 8;

    for (int kt = 0; kt < KT; kt++) {
        int s = kt & 1;
        if (kt + 1 < KT) {
            int s2 = s ^ 1;
            hg64_load_tile(A, B, As + s2 * 128 * APITCH, Bs + s2 * 32 * BPITCH64,
                           (kt + 1) * 32, bm, bn, K, N,
                           a_ld_row, a_ld_col, b_ld_row, b_ld_col);
            cp_commit();
            cp_wait1();
        } else {
            cp_wait0();
        }
        __syncthreads();

        f16* As_s = As + s * 128 * APITCH;
        f16* Bs_s = Bs + s * 32 * BPITCH64;

#pragma unroll
        for (int kk = 0; kk < 2; kk++) {
            u32 a_frag[2][4];
            u32 b_frag[2][4];
#pragma unroll
            for (int mi = 0; mi < 2; mi++) {
                u32 addr = (u32)__cvta_generic_to_shared(
                    As_s + (a_row + mi * 16) * APITCH + kk * 16 + a_csel);
                ldsm_x4(a_frag[mi][0], a_frag[mi][1], a_frag[mi][2], a_frag[mi][3], addr);
            }
#pragma unroll
            for (int ng = 0; ng < 2; ng++) {
                u32 addr = (u32)__cvta_generic_to_shared(
                    Bs_s + (kk * 16 + b_row) * BPITCH64 + ng * 16 + b_csel);
                ldsm_x4_t(b_frag[ng][0], b_frag[ng][1], b_frag[ng][2], b_frag[ng][3], addr);
            }
#pragma unroll
            for (int mi = 0; mi < 2; mi++) {
#pragma unroll
                for (int ng = 0; ng < 2; ng++) {
                    mma_f16(acc[mi][2 * ng],     a_frag[mi], b_frag[ng][0], b_frag[ng][1]);
                    mma_f16(acc[mi][2 * ng + 1], a_frag[mi], b_frag[ng][2], b_frag[ng][3]);
                }
            }
        }
        __syncthreads();
    }

    int gID = lane >> 2;
    int tig = lane & 3;
#pragma unroll
    for (int mi = 0; mi < 2; mi++) {
        int row0 = bm * 128 + wm * 32 + mi * 16 + gID;
#pragma unroll
        for (int nj = 0; nj < 4; nj++) {
            int col = bn * 64 + wn * 32 + nj * 8 + tig * 2;
            float v0 = acc[mi][nj][0];
            float v1 = acc[mi][nj][1];
            float v2 = acc[mi][nj][2];
            float v3 = acc[mi][nj][3];
            if (bias != 0) {
                float b0 = bias[col];
                float b1 = bias[col + 1];
                v0 += b0; v1 += b1; v2 += b0; v3 += b1;
            }
            if (EPI == EPI_GELU) {
                v0 = 0.5f * v0 * (1.0f + erff(v0 * 0.70710678118654752f));
                v1 = 0.5f * v1 * (1.0f + erff(v1 * 0.70710678118654752f));
                v2 = 0.5f * v2 * (1.0f + erff(v2 * 0.70710678118654752f));
                v3 = 0.5f * v3 * (1.0f + erff(v3 * 0.70710678118654752f));
            }
            if (EPI == EPI_RES) {
                v0 += res[(size_t)row0 * N + col];
                v1 += res[(size_t)row0 * N + col + 1];
                v2 += res[(size_t)(row0 + 8) * N + col];
                v3 += res[(size_t)(row0 + 8) * N + col + 1];
            }
            if (OUTMODE == 2) {
                f16* C = (f16*)Cout;
                *(__half2*)(C + (size_t)row0 * N + col) = __floats2half2_rn(v0, v1);
                *(__half2*)(C + (size_t)(row0 + 8) * N + col) = __floats2half2_rn(v2, v3);
            } else {
                float* C = (float*)Cout;
                C[(size_t)row0 * N + col] = v0;
                C[(size_t)row0 * N + col + 1] = v1;
                C[(size_t)(row0 + 8) * N + col] = v2;
                C[(size_t)(row0 + 8) * N + col + 1] = v3;
            }
        }
    }
}

// ---------------------------------------------------------------------------
// Flash attention (verified round 14)
// ---------------------------------------------------------------------------
#define FAPITCH 72

__global__ __launch_bounds__(256) void fattn_kernel(
    const f16* __restrict__ q, const f16* __restrict__ k,
    const f16* __restrict__ v, const int* __restrict__ cu,
    f16* __restrict__ outp, int ldqkv) {
    __shared__ f16 Qs[128 * FAPITCH];
    __shared__ f16 Ks[64 * FAPITCH];
    __shared__ f16 Vs[64 * FAPITCH];

    int h = blockIdx.y;
    int q0 = blockIdx.x * 128;

    int g = 0;
    for (int i = 0; i < NSEG; i++) {
        if (cu[i] <= q0) g = i;
    }
    int s0 = cu[g];
    int s1 = cu[g + 1];
    int len = s1 - s0;
    if (len > 512) len = 512;
    int nchunks = (len + 63) >> 6;

    int tid = threadIdx.x;
    int lane = tid & 31;
    int warp = tid >> 5;
    int gID = lane >> 2;
    int tig = lane & 3;
    int m0 = warp * 16;
    const float scale = 0.125f;

#pragma unroll
    for (int t = 0; t < 4; t++) {
        int gi = tid + t * 256;
        int i = gi >> 3;
        int c8 = (gi & 7) * 8;
        uint4 qv = *(const uint4*)(q + (size_t)(q0 + i) * ldqkv + h * HDIM + c8);
        *(uint4*)(Qs + i * FAPITCH + c8) = qv;
    }
    __syncthreads();

    u32 qa[4][4];
#pragma unroll
    for (int ks = 0; ks < 4; ks++) {
        u32 addr = (u32)__cvta_generic_to_shared(
            Qs + (m0 + (lane & 15)) * FAPITCH + ks * 16 + (lane >> 4) * 8);
        ldsm_x4(qa[ks][0], qa[ks][1], qa[ks][2], qa[ks][3], addr);
    }

    float mrun0 = -FLT_MAX, mrun1 = -FLT_MAX;
    float lrun0 = 0.f, lrun1 = 0.f;
    float acco[8][4];
#pragma unroll
    for (int nt = 0; nt < 8; nt++) {
#pragma unroll
        for (int e = 0; e < 4; e++) acco[nt][e] = 0.f;
    }

    for (int c = 0; c < nchunks; c++) {
        __syncthreads();
#pragma unroll
        for (int t = 0; t < 2; t++) {
            int gi = tid + t * 256;
            int j = gi >> 3;
            int c8 = (gi & 7) * 8;
            int row = s0 + c * 64 + j;
            uint4 kv = make_uint4(0u, 0u, 0u, 0u);
            uint4 vv = make_uint4(0u, 0u, 0u, 0u);
            if (row < s1) {
                kv = *(const uint4*)(k + (size_t)row * ldqkv + h * HDIM + c8);
                vv = *(const uint4*)(v + (size_t)row * ldqkv + h * HDIM + c8);
            }
            *(uint4*)(Ks + j * FAPITCH + c8) = kv;
            *(uint4*)(Vs + j * FAPITCH + c8) = vv;
        }
        __syncthreads();

        float sacc[8][4];
#pragma unroll
        for (int nt = 0; nt < 8; nt++) {
#pragma unroll
            for (int e = 0; e < 4; e++) sacc[nt][e] = 0.f;
        }
#pragma unroll
        for (int ks = 0; ks < 4; ks++) {
#pragma unroll
            for (int ng = 0; ng < 4; ng++) {
                u32 r0, r1, r2, r3;
                u32 addr = (u32)__cvta_generic_to_shared(
                    Ks + (ng * 16 + (lane & 15)) * FAPITCH + ks * 16 + (lane >> 4) * 8);
                ldsm_x4(r0, r1, r2, r3, addr);
                mma_f16_s(sacc[ng * 2],     qa[ks][0], qa[ks][1], qa[ks][2], qa[ks][3], r0, r2);
                mma_f16_s(sacc[ng * 2 + 1], qa[ks][0], qa[ks][1], qa[ks][2], qa[ks][3], r1, r3);
            }
        }

        bool tail = (c * 64 + 64 > len);
#pragma unroll
        for (int nt = 0; nt < 8; nt++) {
            sacc[nt][0] *= scale;
            sacc[nt][1] *= scale;
            sacc[nt][2] *= scale;
            sacc[nt][3] *= scale;
            if (tail) {
                int col = c * 64 + nt * 8 + tig * 2;
                if (col >= len)     { sacc[nt][0] = -FLT_MAX; sacc[nt][2] = -FLT_MAX; }
                if (col + 1 >= len) { sacc[nt][1] = -FLT_MAX; sacc[nt][3] = -FLT_MAX; }
            }
        }

        float mx0 = mrun0, mx1 = mrun1;
#pragma unroll
        for (int nt = 0; nt < 8; nt++) {
            mx0 = fmaxf(mx0, fmaxf(sacc[nt][0], sacc[nt][1]));
            mx1 = fmaxf(mx1, fmaxf(sacc[nt][2], sacc[nt][3]));
        }
        mx0 = fmaxf(mx0, __shfl_xor_sync(0xffffffff, mx0, 1));
        mx0 = fmaxf(mx0, __shfl_xor_sync(0xffffffff, mx0, 2));
        mx1 = fmaxf(mx1, __shfl_xor_sync(0xffffffff, mx1, 1));
        mx1 = fmaxf(mx1, __shfl_xor_sync(0xffffffff, mx1, 2));

        float alpha0 = __expf(mrun0 - mx0);
        float alpha1 = __expf(mrun1 - mx1);

        float p[8][4];
        float ps0 = 0.f, ps1 = 0.f;
#pragma unroll
        for (int nt = 0; nt < 8; nt++) {
            p[nt][0] = __expf(sacc[nt][0] - mx0);
            p[nt][1] = __expf(sacc[nt][1] - mx0);
            p[nt][2] = __expf(sacc[nt][2] - mx1);
            p[nt][3] = __expf(sacc[nt][3] - mx1);
            ps0 += p[nt][0] + p[nt][1];
            ps1 += p[nt][2] + p[nt][3];
        }
        ps0 += __shfl_xor_sync(0xffffffff, ps0, 1);
        ps0 += __shfl_xor_sync(0xffffffff, ps0, 2);
        ps1 += __shfl_xor_sync(0xffffffff, ps1, 1);
        ps1 += __shfl_xor_sync(0xffffffff, ps1, 2);

        lrun0 = lrun0 * alpha0 + ps0;
        lrun1 = lrun1 * alpha1 + ps1;
        mrun0 = mx0;
        mrun1 = mx1;

#pragma unroll
        for (int nt = 0; nt < 8; nt++) {
            acco[nt][0] *= alpha0;
            acco[nt][1] *= alpha0;
            acco[nt][2] *= alpha1;
            acco[nt][3] *= alpha1;
        }

#pragma unroll
        for (int kk = 0; kk < 4; kk++) {
            __half2 h0 = __floats2half2_rn(p[2 * kk][0], p[2 * kk][1]);
            __half2 h1 = __floats2half2_rn(p[2 * kk][2], p[2 * kk][3]);
            __half2 h2 = __floats2half2_rn(p[2 * kk + 1][0], p[2 * kk + 1][1]);
            __half2 h3 = __floats2half2_rn(p[2 * kk + 1][2], p[2 * kk + 1][3]);
            u32 pa0 = *(u32*)&h0;
            u32 pa1 = *(u32*)&h1;
            u32 pa2 = *(u32*)&h2;
            u32 pa3 = *(u32*)&h3;
#pragma unroll
            for (int ng = 0; ng < 4; ng++) {
                u32 b0, b1, b2, b3;
                u32 vaddr = (u32)__cvta_generic_to_shared(
                    Vs + (kk * 16 + (lane & 15)) * FAPITCH + ng * 16 + (lane >> 4) * 8);
                ldsm_x4_t(b0, b1, b2, b3, vaddr);
                mma_f16_s(acco[ng * 2],     pa0, pa1, pa2, pa3, b0, b1);
                mma_f16_s(acco[ng * 2 + 1], pa0, pa1, pa2, pa3, b2, b3);
            }
        }
    }

    float inv0 = 1.0f / lrun0;
    float inv1 = 1.0f / lrun1;
    int orow0 = q0 + m0 + gID;
#pragma unroll
    for (int nt = 0; nt < 8; nt++) {
        int col = h * HDIM + nt * 8 + tig * 2;
        *(__half2*)(outp + (size_t)orow0 * DMODEL + col) =
            __floats2half2_rn(acco[nt][0] * inv0, acco[nt][1] * inv0);
        *(__half2*)(outp + (size_t)(orow0 + 8) * DMODEL + col) =
            __floats2half2_rn(acco[nt][2] * inv1, acco[nt][3] * inv1);
    }
}

// ---------------------------------------------------------------------------
// launch (single stream)
// ---------------------------------------------------------------------------
extern "C" void kernel_launch(void* const* d_in, const int* in_sizes, int n_in,
                              void* d_out, int out_size) {
    const float* hidden = (const float*)d_in[0];
    const int*   cu     = (const int*)d_in[1];
    const float* Wq = (const float*)d_in[2];
    const float* bq = (const float*)d_in[3];
    const float* Wk = (const float*)d_in[4];
    const float* Wv = (const float*)d_in[5];
    const float* bv = (const float*)d_in[6];
    const float* Wo = (const float*)d_in[7];
    const float* bo = (const float*)d_in[8];
    const float* ln1_g = (const float*)d_in[9];
    const float* ln1_b = (const float*)d_in[10];
    const float* Wf1 = (const float*)d_in[11];
    const float* bf1 = (const float*)d_in[12];
    const float* Wf2 = (const float*)d_in[13];
    const float* bf2 = (const float*)d_in[14];
    const float* ln2_g = (const float*)d_in[15];
    const float* ln2_b = (const float*)d_in[16];
    float* out = (float*)d_out;

    float *hp, *bqkvp;
    f16 *qkvp, *xlnp, *attnp, *ylnp, *ffnp, *wqkvp, *wop, *wf1p, *wf2p;
    cudaGetSymbolAddress((void**)&qkvp,  g_qkv);
    cudaGetSymbolAddress((void**)&hp,    g_h);
    cudaGetSymbolAddress((void**)&bqkvp, g_bqkv);
    cudaGetSymbolAddress((void**)&xlnp,  g_xln);
    cudaGetSymbolAddress((void**)&attnp, g_attn);
    cudaGetSymbolAddress((void**)&ylnp,  g_yln);
    cudaGetSymbolAddress((void**)&ffnp,  g_ffn);
    cudaGetSymbolAddress((void**)&wqkvp, g_wqkv);
    cudaGetSymbolAddress((void**)&wop,   g_wo);
    cudaGetSymbolAddress((void**)&wf1p,  g_wf1);
    cudaGetSymbolAddress((void**)&wf2p,  g_wf2);

    dim3 blk(256);
    cvt_all_kernel<<<(CVT_TOT + 255) / 256, blk>>>(
        Wq, Wk, Wv, Wo, Wf1, Wf2, wqkvp, wop, wf1p, wf2p);
    pack_bias_kernel<<<(D3 + 255) / 256, blk>>>(bq, bv, bqkvp);

    dim3 gemmQKV(D3 / 128, SEQ / 128);
    dim3 gemmDD64(DMODEL / 64, SEQ / 128);   // 640 blocks (was 320)
    dim3 gemmDF(FFN / 128, SEQ / 128);

    ln_kernel<<<SEQ, blk>>>(hidden, ln1_g, ln1_b, xlnp);
    hgemm_kernel<EPI_BIAS, 2><<<gemmQKV, blk>>>(
        xlnp, wqkvp, bqkvp, 0, qkvp, SEQ, D3, DMODEL);
    fattn_kernel<<<dim3(SEQ / 128, NHEAD), blk>>>(
        qkvp, qkvp + DMODEL, qkvp + 2 * DMODEL, cu, attnp, D3);
    hgemm64_kernel<EPI_RES, 0><<<gemmDD64, blk>>>(
        attnp, wop, bo, hidden, hp, SEQ, DMODEL, DMODEL);
    ln_kernel<<<SEQ, blk>>>(hp, ln2_g, ln2_b, ylnp);
    hgemm_kernel<EPI_GELU, 2><<<gemmDF, blk>>>(
        ylnp, wf1p, bf1, 0, ffnp, SEQ, FFN, DMODEL);
    hgemm64_kernel<EPI_RES, 0><<<gemmDD64, blk>>>(
        ffnp, wf2p, bf2, hp, out, SEQ, DMODEL, FFN);
}